// round 1
// baseline (speedup 1.0000x reference)
#include <cuda_runtime.h>
#include <cuda_bf16.h>
#include <cstdint>

// ---------------------------------------------------------------------------
// Problem constants
// ---------------------------------------------------------------------------
#define BB   16
#define TT   1024
#define DD   512
#define HH   8
#define DHH  64
#define MTOT (BB*TT)        // 16384
#define FF   (4*DD)         // 2048

// ---------------------------------------------------------------------------
// Device scratch (allocation-free rule: __device__ globals)
// ---------------------------------------------------------------------------
__device__ float g_q  [MTOT*DD];            // 32 MB
__device__ float g_k  [MTOT*DD];            // 32 MB
__device__ float g_v  [MTOT*DD];            // 32 MB
__device__ float g_res[MTOT*DD];            // 32 MB
__device__ float g_s  [(size_t)BB*HH*TT*TT];// 512 MB scores
__device__ float g_S1 [BB*FF];              // relu(h1) column sums per batch

// ---------------------------------------------------------------------------
// Generic tiled fp32 GEMM.
//   C[m][n] = alpha * sum_k A[m][k] * (TB ? Bphys[n][k] : Bphys[k][n])
// Batched via blockIdx.z decomposed as zo = z/ZI, zi = z%ZI with per-matrix
// (outer, inner) element strides. No bounds checks: all dims divide tiles.
// EPI: 0 = store alpha*acc
//      1 = relu + per-batch column sum into S1 (no C store)
//      2 = store acc + R   (R shares C's offset/ld)
// ---------------------------------------------------------------------------
template<int BM, int BN, int BK, int TM, int TN, bool TB, int EPI>
__global__ __launch_bounds__(256)
void gemm_k(const float* __restrict__ A, int lda, long sAo, long sAi,
            const float* __restrict__ B, int ldb, long sBo, long sBi,
            float*       __restrict__ C, int ldc, long sCo, long sCi,
            const float* __restrict__ R,
            float*       __restrict__ S1, int ldS, int Tdim,
            int K, float alpha, int ZI)
{
    __shared__ float As[BK][BM + 4];
    __shared__ float Bs[BK][BN + 4];

    const int zi = blockIdx.z % ZI;
    const int zo = blockIdx.z / ZI;
    const float* Ab = A + (long)zo * sAo + (long)zi * sAi;
    const float* Bb = B + (long)zo * sBo + (long)zi * sBi;
    const long   coff = (long)zo * sCo + (long)zi * sCi;

    const int m0 = blockIdx.y * BM;
    const int n0 = blockIdx.x * BN;
    const int tid = threadIdx.x;
    const int tx = tid % (BN / TN);   // 16
    const int ty = tid / (BN / TN);   // 16

    float acc[TM][TN];
#pragma unroll
    for (int i = 0; i < TM; i++)
#pragma unroll
        for (int j = 0; j < TN; j++) acc[i][j] = 0.f;

    for (int k0 = 0; k0 < K; k0 += BK) {
        // ---- load A tile (BM x BK), store transposed As[k][m] ----
#pragma unroll
        for (int i = tid * 4; i < BM * BK; i += 256 * 4) {
            int m  = i / BK;
            int kk = i % BK;
            float4 t4 = *(const float4*)(Ab + (long)(m0 + m) * lda + (k0 + kk));
            As[kk + 0][m] = t4.x;
            As[kk + 1][m] = t4.y;
            As[kk + 2][m] = t4.z;
            As[kk + 3][m] = t4.w;
        }
        // ---- load B tile ----
        if constexpr (!TB) {
#pragma unroll
            for (int i = tid * 4; i < BK * BN; i += 256 * 4) {
                int kk = i / BN;
                int n  = i % BN;
                float4 t4 = *(const float4*)(Bb + (long)(k0 + kk) * ldb + (n0 + n));
                *(float4*)&Bs[kk][n] = t4;
            }
        } else {
#pragma unroll
            for (int i = tid * 4; i < BK * BN; i += 256 * 4) {
                int n  = i / BK;
                int kk = i % BK;
                float4 t4 = *(const float4*)(Bb + (long)(n0 + n) * ldb + (k0 + kk));
                Bs[kk + 0][n] = t4.x;
                Bs[kk + 1][n] = t4.y;
                Bs[kk + 2][n] = t4.z;
                Bs[kk + 3][n] = t4.w;
            }
        }
        __syncthreads();

#pragma unroll
        for (int kk = 0; kk < BK; kk++) {
            float4 a0 = *(float4*)&As[kk][ty * TM];
            float4 a1 = *(float4*)&As[kk][ty * TM + 4];
            float4 b0 = *(float4*)&Bs[kk][tx * TN];
            float a[TM] = {a0.x, a0.y, a0.z, a0.w, a1.x, a1.y, a1.z, a1.w};
            float b[TN] = {b0.x, b0.y, b0.z, b0.w};
#pragma unroll
            for (int i = 0; i < TM; i++)
#pragma unroll
                for (int j = 0; j < TN; j++) acc[i][j] += a[i] * b[j];
        }
        __syncthreads();
    }

    if constexpr (EPI == 1) {
        // relu + column-sum into S1[batch][n]
        __shared__ float cs[BN];
        if (tid < BN) cs[tid] = 0.f;
        __syncthreads();
#pragma unroll
        for (int j = 0; j < TN; j++) {
            float ssum = 0.f;
#pragma unroll
            for (int i = 0; i < TM; i++) ssum += fmaxf(acc[i][j], 0.f);
            atomicAdd(&cs[tx * TN + j], ssum);
        }
        __syncthreads();
        if (tid < BN) {
            int b = m0 / Tdim;
            atomicAdd(&S1[b * ldS + n0 + tid], cs[tid]);
        }
    } else {
        float* Cb = C + coff;
#pragma unroll
        for (int i = 0; i < TM; i++) {
            long row = (long)(m0 + ty * TM + i) * ldc + n0 + tx * TN;
            float v0 = alpha * acc[i][0];
            float v1 = alpha * acc[i][1];
            float v2 = alpha * acc[i][2];
            float v3 = alpha * acc[i][3];
            if constexpr (EPI == 2) {
                float4 r4 = *(const float4*)(R + coff + row);
                v0 += r4.x; v1 += r4.y; v2 += r4.z; v3 += r4.w;
            }
            *(float4*)&Cb[row] = make_float4(v0, v1, v2, v3);
        }
    }
}

// ---------------------------------------------------------------------------
// Row softmax with diagonal blinding (col == row -> probability exactly 0).
// One block (256 thr) per row; each thread holds 4 values.
// ---------------------------------------------------------------------------
__global__ __launch_bounds__(256)
void softmax_diag_k(float* __restrict__ S)
{
    const int t  = blockIdx.x;                       // row within T
    const long base = ((long)blockIdx.y * TT + t) * TT;
    const int tid = threadIdx.x;
    const float NEGINF = __int_as_float(0xff800000);

    float4 v = *(float4*)(S + base + tid * 4);
    float x[4] = {v.x, v.y, v.z, v.w};
    const int c0 = tid * 4;
#pragma unroll
    for (int j = 0; j < 4; j++)
        if (c0 + j == t) x[j] = NEGINF;

    float m = fmaxf(fmaxf(x[0], x[1]), fmaxf(x[2], x[3]));
#pragma unroll
    for (int o = 16; o; o >>= 1) m = fmaxf(m, __shfl_xor_sync(0xffffffffu, m, o));

    __shared__ float redm[8];
    __shared__ float reds[8];
    const int w = tid >> 5, l = tid & 31;
    if (l == 0) redm[w] = m;
    __syncthreads();
    float bm = redm[0];
#pragma unroll
    for (int i = 1; i < 8; i++) bm = fmaxf(bm, redm[i]);

    float e[4];
    float ssum = 0.f;
#pragma unroll
    for (int j = 0; j < 4; j++) { e[j] = __expf(x[j] - bm); ssum += e[j]; }
#pragma unroll
    for (int o = 16; o; o >>= 1) ssum += __shfl_xor_sync(0xffffffffu, ssum, o);
    if (l == 0) reds[w] = ssum;
    __syncthreads();
    float bs = 0.f;
#pragma unroll
    for (int i = 0; i < 8; i++) bs += reds[i];

    const float inv = 1.0f / bs;
    *(float4*)(S + base + tid * 4) =
        make_float4(e[0] * inv, e[1] * inv, e[2] * inv, e[3] * inv);
}

// ---------------------------------------------------------------------------
__global__ void zero_k(float* __restrict__ p, int n)
{
    int i = blockIdx.x * blockDim.x + threadIdx.x;
    if (i < n) p[i] = 0.f;
}

// ---------------------------------------------------------------------------
// Final: out[b,d] = mean_t(res[b,t,d]) + (S1[b,:]/T) @ fw2[:,d]
// ---------------------------------------------------------------------------
__global__ __launch_bounds__(512)
void final_k(const float* __restrict__ res, const float* __restrict__ S1,
             const float* __restrict__ fw2, float* __restrict__ out)
{
    __shared__ float s1s[FF];
    const int b = blockIdx.x;
    const int d = threadIdx.x;
    for (int i = threadIdx.x; i < FF; i += 512)
        s1s[i] = S1[b * FF + i] * (1.0f / (float)TT);
    __syncthreads();

    float acc = 0.f;
    const float* rb = res + (long)b * TT * DD + d;
#pragma unroll 4
    for (int t = 0; t < TT; t++) acc += rb[(long)t * DD];
    acc *= 1.0f / (float)TT;

#pragma unroll 4
    for (int f = 0; f < FF; f++) acc += s1s[f] * fw2[(long)f * DD + d];

    out[b * DD + d] = acc;
}

// ---------------------------------------------------------------------------
// Launch
// ---------------------------------------------------------------------------
extern "C" void kernel_launch(void* const* d_in, const int* in_sizes, int n_in,
                              void* d_out, int out_size)
{
    const float* queries = (const float*)d_in[0];
    const float* keys    = (const float*)d_in[1];
    const float* Wq      = (const float*)d_in[2];
    const float* Wk      = (const float*)d_in[3];
    const float* Wv      = (const float*)d_in[4];
    const float* fw1     = (const float*)d_in[5];
    const float* fw2     = (const float*)d_in[6];
    float* out = (float*)d_out;

    float *q, *k, *v, *s, *res, *S1;
    cudaGetSymbolAddress((void**)&q,   g_q);
    cudaGetSymbolAddress((void**)&k,   g_k);
    cudaGetSymbolAddress((void**)&v,   g_v);
    cudaGetSymbolAddress((void**)&s,   g_s);
    cudaGetSymbolAddress((void**)&res, g_res);
    cudaGetSymbolAddress((void**)&S1,  g_S1);

    const dim3 blk(256);
    const long TD   = (long)TT * DD;          // 524288
    const long TT2  = (long)TT * TT;          // 1048576

    // 1) q = queries @ Wq         [16384,512] = [16384,512]@[512,512]
    gemm_k<128,64,16,8,4,false,0><<<dim3(DD/64, MTOT/128, 1), blk>>>(
        queries, DD, 0, 0,  Wq, DD, 0, 0,  q, DD, 0, 0,
        nullptr, nullptr, 0, 0, DD, 1.0f, 1);

    // 2) k = keys @ Wk
    gemm_k<128,64,16,8,4,false,0><<<dim3(DD/64, MTOT/128, 1), blk>>>(
        keys, DD, 0, 0,  Wk, DD, 0, 0,  k, DD, 0, 0,
        nullptr, nullptr, 0, 0, DD, 1.0f, 1);

    // 3) v = k_proj @ Wv   (faithful to source: V from projected keys)
    gemm_k<128,64,16,8,4,false,0><<<dim3(DD/64, MTOT/128, 1), blk>>>(
        k, DD, 0, 0,  Wv, DD, 0, 0,  v, DD, 0, 0,
        nullptr, nullptr, 0, 0, DD, 1.0f, 1);

    // 4) zero S1
    zero_k<<<(BB*FF + 1023)/1024, 1024>>>(S1, BB*FF);

    // 5) scores: S[bh] = (Qh @ Khᵀ) / 8     z = b*H + h  (zo=b, zi=h)
    //    Qh,Kh are [T,DH] views with row stride D; S[bh] is [T,T] contiguous.
    gemm_k<128,64,16,8,4,true,0><<<dim3(TT/64, TT/128, BB*HH), blk>>>(
        q, DD, TD, DHH,   k, DD, TD, DHH,   s, TT, (long)HH*TT2, TT2,
        nullptr, nullptr, 0, 0, DHH, 0.125f, HH);

    // 6) softmax with diagonal blinding, in place
    softmax_diag_k<<<dim3(TT, BB*HH), 256>>>(s);

    // 7) res = P @ Vh + queries (residual fused), written into head slices
    gemm_k<128,64,16,8,4,false,2><<<dim3(DHH/64, TT/128, BB*HH), blk>>>(
        s, TT, (long)HH*TT2, TT2,   v, DD, TD, DHH,   res, DD, TD, DHH,
        queries, nullptr, 0, 0, TT, 1.0f, HH);

    // 8) FFN1 with fused relu + per-batch column sum into S1 (h1 never stored)
    gemm_k<128,64,16,8,4,false,1><<<dim3(FF/64, MTOT/128, 1), blk>>>(
        res, DD, 0, 0,  fw1, FF, 0, 0,  nullptr, 0, 0, 0,
        nullptr, S1, FF, TT, DD, 1.0f, 1);

    // 9) out = mean_t(res) + (S1/T) @ fw2
    final_k<<<BB, 512>>>(res, S1, fw2, out);
}

// round 4
// speedup vs baseline: 1.5226x; 1.5226x over previous
#include <cuda_runtime.h>
#include <cuda_bf16.h>
#include <cstdint>

// ---------------------------------------------------------------------------
// Problem constants
// ---------------------------------------------------------------------------
#define BB   16
#define TT   1024
#define DD   512
#define HH   8
#define DHH  64
#define MTOT (BB*TT)        // 16384
#define FF   (4*DD)         // 2048

typedef __nv_bfloat16 bf16;

// ---------------------------------------------------------------------------
// Device scratch (__device__ globals; allocation-free rule)
// ---------------------------------------------------------------------------
__device__ bf16  g_aq_hi[MTOT*DD], g_aq_mi[MTOT*DD];   // queries bf16 pair
__device__ bf16  g_ak_hi[MTOT*DD], g_ak_mi[MTOT*DD];   // keys bf16 pair
__device__ bf16  g_wqt_hi[DD*DD],  g_wqt_mi[DD*DD];    // Wq^T
__device__ bf16  g_wkt_hi[DD*DD],  g_wkt_mi[DD*DD];
__device__ bf16  g_wvt_hi[DD*DD],  g_wvt_mi[DD*DD];
__device__ bf16  g_f1t_hi[FF*DD],  g_f1t_mi[FF*DD];    // fw1^T [2048,512]
__device__ bf16  g_q_hi[MTOT*DD],  g_q_mi[MTOT*DD];
__device__ bf16  g_k_hi[MTOT*DD],  g_k_mi[MTOT*DD];
__device__ bf16  g_v_hi[MTOT*DD],  g_v_mi[MTOT*DD];
__device__ bf16  g_vt_hi[MTOT*DD], g_vt_mi[MTOT*DD];   // per-b [512,1024]
__device__ bf16  g_res_hi[MTOT*DD], g_res_mi[MTOT*DD];
__device__ float g_s [(size_t)BB*HH*TT*TT];            // 512 MB scores f32
__device__ bf16  g_p_hi[(size_t)BB*HH*TT*TT];          // 256 MB
__device__ bf16  g_p_mi[(size_t)BB*HH*TT*TT];          // 256 MB
__device__ float g_S1[BB*FF];

// ---------------------------------------------------------------------------
// PTX helpers (all base-PTX, sm_80-era: safe under compute_100 target)
// ---------------------------------------------------------------------------
__device__ __forceinline__ uint32_t smem_u32(const void* p) {
    return (uint32_t)__cvta_generic_to_shared((void*)p);
}
__device__ __forceinline__ void cp16(uint32_t dst, const void* src) {
    asm volatile("cp.async.cg.shared.global [%0], [%1], 16;" :: "r"(dst), "l"(src));
}
#define CP_COMMIT() asm volatile("cp.async.commit_group;" ::: "memory")
#define CP_WAIT2()  asm volatile("cp.async.wait_group 2;"  ::: "memory")

__device__ __forceinline__ void ldm_x4(uint32_t* r, uint32_t addr) {
    asm volatile("ldmatrix.sync.aligned.m8n8.x4.shared.b16 {%0,%1,%2,%3}, [%4];"
        : "=r"(r[0]), "=r"(r[1]), "=r"(r[2]), "=r"(r[3]) : "r"(addr));
}
__device__ __forceinline__ void ldm_x2(uint32_t* r, uint32_t addr) {
    asm volatile("ldmatrix.sync.aligned.m8n8.x2.shared.b16 {%0,%1}, [%2];"
        : "=r"(r[0]), "=r"(r[1]) : "r"(addr));
}
__device__ __forceinline__ void mma16816(float* c, const uint32_t* a, const uint32_t* b) {
    asm volatile(
        "mma.sync.aligned.m16n8k16.row.col.f32.bf16.bf16.f32 "
        "{%0,%1,%2,%3}, {%4,%5,%6,%7}, {%8,%9}, {%0,%1,%2,%3};"
        : "+f"(c[0]), "+f"(c[1]), "+f"(c[2]), "+f"(c[3])
        : "r"(a[0]), "r"(a[1]), "r"(a[2]), "r"(a[3]), "r"(b[0]), "r"(b[1]));
}

// ---------------------------------------------------------------------------
// bf16 mma.sync GEMM.  D[m][n] = sum_k A[m][k]*B[n][k], A [M,K] row-major,
// B [N,K] n-major (so mma's col-major B fragment loads non-trans).
// A,B given as (hi, mid) bf16 pairs; 3 passes Ah*Bh + Ah*Bm + Am*Bh.
// CTA tile 128 x BN, BK=32, 8 warps (2x4), 3-stage cp.async pipeline.
// EPI 0: C = alpha*D (+R residual f32) -> bf16 (hi,mid) pair
// EPI 1: Cf = alpha*D (f32)
// EPI 2: relu(D) column sums atomically into S1[b*FF + n]
// ---------------------------------------------------------------------------
template<int BN, int EPI>
__global__ __launch_bounds__(256)
void gemm_mma(const bf16* __restrict__ Ahi, const bf16* __restrict__ Ami,
              int ldA, long sAo, long sAi,
              const bf16* __restrict__ Bhi, const bf16* __restrict__ Bmi,
              int ldB, long sBo, long sBi,
              float alpha, int K, int ZI,
              bf16* __restrict__ Chi, bf16* __restrict__ Cmi, int ldc,
              long sCo, long sCi,
              const float* __restrict__ Rres,
              float* __restrict__ Cf,
              float* __restrict__ S1)
{
    constexpr int BM = 128, BK = 32, LDS = 40;       // 80B row pitch
    constexpr int NT = BN / 4;                       // warp n-tile
    constexpr int NF = NT / 8;                       // n-frags per warp
    constexpr int MF = 4;                            // m-frags per warp (64/16)
    constexpr int AELEMS = 2 * BM * LDS;             // hi+mi
    constexpr int BELEMS = 2 * BN * LDS;
    constexpr int STAGE  = AELEMS + BELEMS;

    extern __shared__ bf16 sm[];
    const int tid = threadIdx.x, lane = tid & 31, wid = tid >> 5;
    const int wm = wid >> 2, wn = wid & 3;
    const int g = lane >> 2, t4 = lane & 3;

    const int z = blockIdx.z, zo = z / ZI, zi = z % ZI;
    const int m0 = blockIdx.y * BM, n0 = blockIdx.x * BN;

    const bf16* Ah = Ahi + (long)zo * sAo + (long)zi * sAi + (long)m0 * ldA;
    const bf16* Am = Ami + (long)zo * sAo + (long)zi * sAi + (long)m0 * ldA;
    const bf16* Bh = Bhi + (long)zo * sBo + (long)zi * sBi + (long)n0 * ldB;
    const bf16* Bm = Bmi + (long)zo * sBo + (long)zi * sBi + (long)n0 * ldB;

    const int NC = K / BK;

    auto load_chunk = [&](int c) {
        if (c < NC) {
            bf16* st = sm + (c % 3) * STAGE;
            const long koff = (long)c * BK;
            // A: 2(sel) * 128 rows * 4 quarters of 16B  (BK=32 bf16 = 64B/row)
            for (int i = tid; i < 1024; i += 256) {
                int sel = i >> 9, j = i & 511, r = j >> 2, hh = j & 3;
                const bf16* src = (sel ? Am : Ah) + (long)r * ldA + koff + hh * 8;
                cp16(smem_u32(st + sel * (BM * LDS) + r * LDS + hh * 8), src);
            }
            // B: 2(sel) * BN rows * 4 quarters
            for (int i = tid; i < BN * 8; i += 256) {
                int sel = i >= BN * 4;
                int j = sel ? i - BN * 4 : i;
                int r = j >> 2, hh = j & 3;
                const bf16* src = (sel ? Bm : Bh) + (long)r * ldB + koff + hh * 8;
                cp16(smem_u32(st + AELEMS + sel * (BN * LDS) + r * LDS + hh * 8), src);
            }
        }
        CP_COMMIT();   // empty groups keep the wait_group accounting uniform
    };

    float acc[MF][NF][4];
#pragma unroll
    for (int i = 0; i < MF; i++)
#pragma unroll
        for (int j = 0; j < NF; j++)
#pragma unroll
            for (int e = 0; e < 4; e++) acc[i][j][e] = 0.f;

    load_chunk(0);
    load_chunk(1);

    for (int c = 0; c < NC; c++) {
        load_chunk(c + 2);
        CP_WAIT2();              // groups issued = c+3; <=2 pending => chunk c done
        __syncthreads();

        bf16* st = sm + (c % 3) * STAGE;
        const uint32_t aH = smem_u32(st);
        const uint32_t aM = smem_u32(st + BM * LDS);
        const uint32_t bH = smem_u32(st + AELEMS);
        const uint32_t bM = smem_u32(st + AELEMS + BN * LDS);

#pragma unroll
        for (int ks = 0; ks < 2; ks++) {
            uint32_t ah[MF][4], am[MF][4], bh[NF][2], bm[NF][2];
            const int acol = ks * 16 + ((lane >> 4) << 3);
            const int ar   = lane & 15;
#pragma unroll
            for (int mf = 0; mf < MF; mf++) {
                int off = (wm * 64 + mf * 16 + ar) * LDS + acol;
                ldm_x4(ah[mf], aH + off * 2);
                ldm_x4(am[mf], aM + off * 2);
            }
            const int bcol = ks * 16 + (((lane >> 3) & 1) << 3);
            const int br   = lane & 7;
#pragma unroll
            for (int nf = 0; nf < NF; nf++) {
                int off = (wn * NT + nf * 8 + br) * LDS + bcol;
                ldm_x2(bh[nf], bH + off * 2);
                ldm_x2(bm[nf], bM + off * 2);
            }
#pragma unroll
            for (int mf = 0; mf < MF; mf++)
#pragma unroll
                for (int nf = 0; nf < NF; nf++) {
                    mma16816(acc[mf][nf], ah[mf], bh[nf]);
                    mma16816(acc[mf][nf], ah[mf], bm[nf]);
                    mma16816(acc[mf][nf], am[mf], bh[nf]);
                }
        }
        __syncthreads();
    }

    // ---------------- epilogue ----------------
    if constexpr (EPI == 2) {
        float* cs = (float*)sm;
        if (tid < BN) cs[tid] = 0.f;
        __syncthreads();
#pragma unroll
        for (int nf = 0; nf < NF; nf++) {
            float s0 = 0.f, s1 = 0.f;
#pragma unroll
            for (int mf = 0; mf < MF; mf++) {
                s0 += fmaxf(acc[mf][nf][0], 0.f) + fmaxf(acc[mf][nf][2], 0.f);
                s1 += fmaxf(acc[mf][nf][1], 0.f) + fmaxf(acc[mf][nf][3], 0.f);
            }
            int col = wn * NT + nf * 8 + t4 * 2;
            atomicAdd(&cs[col], s0);
            atomicAdd(&cs[col + 1], s1);
        }
        __syncthreads();
        if (tid < BN)
            atomicAdd(&S1[(m0 / TT) * FF + n0 + tid], cs[tid]);
    } else if constexpr (EPI == 1) {
        float* Cb = Cf + (long)zo * sCo + (long)zi * sCi;
#pragma unroll
        for (int mf = 0; mf < MF; mf++)
#pragma unroll
            for (int nf = 0; nf < NF; nf++) {
                long o0 = (long)(m0 + wm * 64 + mf * 16 + g) * ldc
                        + n0 + wn * NT + nf * 8 + t4 * 2;
                *(float2*)&Cb[o0] =
                    make_float2(alpha * acc[mf][nf][0], alpha * acc[mf][nf][1]);
                *(float2*)&Cb[o0 + 8 * (long)ldc] =
                    make_float2(alpha * acc[mf][nf][2], alpha * acc[mf][nf][3]);
            }
    } else {
        bf16* Ch = Chi + (long)zo * sCo + (long)zi * sCi;
        bf16* Cm = Cmi + (long)zo * sCo + (long)zi * sCi;
        const float* Rb = Rres ? Rres + (long)zo * sCo + (long)zi * sCi : nullptr;
#pragma unroll
        for (int mf = 0; mf < MF; mf++)
#pragma unroll
            for (int nf = 0; nf < NF; nf++) {
#pragma unroll
                for (int half = 0; half < 2; half++) {
                    long o0 = (long)(m0 + wm * 64 + mf * 16 + g + half * 8) * ldc
                            + n0 + wn * NT + nf * 8 + t4 * 2;
                    float v0 = alpha * acc[mf][nf][half * 2 + 0];
                    float v1 = alpha * acc[mf][nf][half * 2 + 1];
                    if (Rb) {
                        float2 r2 = *(const float2*)&Rb[o0];
                        v0 += r2.x; v1 += r2.y;
                    }
                    bf16 h0 = __float2bfloat16(v0);
                    bf16 h1 = __float2bfloat16(v1);
                    __nv_bfloat162 ph = __halves2bfloat162(h0, h1);
                    __nv_bfloat162 pm = __halves2bfloat162(
                        __float2bfloat16(v0 - __bfloat162float(h0)),
                        __float2bfloat16(v1 - __bfloat162float(h1)));
                    *(uint32_t*)&Ch[o0] = *(uint32_t*)&ph;
                    *(uint32_t*)&Cm[o0] = *(uint32_t*)&pm;
                }
            }
    }
}

// ---------------------------------------------------------------------------
// f32 -> bf16 (hi, mid) pair
// ---------------------------------------------------------------------------
__global__ void cvt_k(const float* __restrict__ in, bf16* __restrict__ oh,
                      bf16* __restrict__ om, int n)
{
    int i = blockIdx.x * blockDim.x + threadIdx.x;
    if (i < n) {
        float x = in[i];
        bf16 h = __float2bfloat16(x);
        oh[i] = h;
        om[i] = __float2bfloat16(x - __bfloat162float(h));
    }
}

// f32 [R,C] -> bf16 pair, transposed [C,R]
__global__ void trcvt_k(const float* __restrict__ in, bf16* __restrict__ oh,
                        bf16* __restrict__ om, int R, int C)
{
    __shared__ float tile[32][33];
    int r0 = blockIdx.y * 32, c0 = blockIdx.x * 32;
    for (int i = threadIdx.y; i < 32; i += 8)
        tile[i][threadIdx.x] = in[(long)(r0 + i) * C + c0 + threadIdx.x];
    __syncthreads();
    for (int i = threadIdx.y; i < 32; i += 8) {
        float x = tile[threadIdx.x][i];
        bf16 h = __float2bfloat16(x);
        long dst = (long)(c0 + i) * R + r0 + threadIdx.x;
        oh[dst] = h;
        om[dst] = __float2bfloat16(x - __bfloat162float(h));
    }
}

// v [b*1024+t, 512] bf16 pair -> vt[b][d][t] ([512,1024] per b)
__global__ void transpose_pair_k(const bf16* __restrict__ vh, const bf16* __restrict__ vm,
                                 bf16* __restrict__ oh, bf16* __restrict__ om)
{
    __shared__ bf16 th[32][33], tm[32][33];
    int b = blockIdx.z;
    int t0 = blockIdx.x * 32, d0 = blockIdx.y * 32;
    for (int i = threadIdx.y; i < 32; i += 8) {
        long src = ((long)(b * TT + t0 + i)) * DD + d0 + threadIdx.x;
        th[i][threadIdx.x] = vh[src];
        tm[i][threadIdx.x] = vm[src];
    }
    __syncthreads();
    for (int i = threadIdx.y; i < 32; i += 8) {
        long dst = (long)b * DD * TT + (long)(d0 + i) * TT + t0 + threadIdx.x;
        oh[dst] = th[threadIdx.x][i];
        om[dst] = tm[threadIdx.x][i];
    }
}

// ---------------------------------------------------------------------------
// Row softmax with diagonal blinding; output as bf16 (hi, mid) pair.
// ---------------------------------------------------------------------------
__global__ __launch_bounds__(256)
void softmax_diag_k(const float* __restrict__ S, bf16* __restrict__ Ph,
                    bf16* __restrict__ Pm)
{
    const int t = blockIdx.x;
    const long base = ((long)blockIdx.y * TT + t) * TT;
    const int tid = threadIdx.x;
    const float NEGINF = __int_as_float(0xff800000);

    float4 v = *(const float4*)(S + base + tid * 4);
    float x[4] = {v.x, v.y, v.z, v.w};
    const int c0 = tid * 4;
#pragma unroll
    for (int j = 0; j < 4; j++)
        if (c0 + j == t) x[j] = NEGINF;

    float m = fmaxf(fmaxf(x[0], x[1]), fmaxf(x[2], x[3]));
#pragma unroll
    for (int o = 16; o; o >>= 1) m = fmaxf(m, __shfl_xor_sync(0xffffffffu, m, o));

    __shared__ float redm[8], reds[8];
    const int w = tid >> 5, l = tid & 31;
    if (l == 0) redm[w] = m;
    __syncthreads();
    float bm = redm[0];
#pragma unroll
    for (int i = 1; i < 8; i++) bm = fmaxf(bm, redm[i]);

    float e[4], ssum = 0.f;
#pragma unroll
    for (int j = 0; j < 4; j++) { e[j] = __expf(x[j] - bm); ssum += e[j]; }
#pragma unroll
    for (int o = 16; o; o >>= 1) ssum += __shfl_xor_sync(0xffffffffu, ssum, o);
    if (l == 0) reds[w] = ssum;
    __syncthreads();
    float bs = 0.f;
#pragma unroll
    for (int i = 0; i < 8; i++) bs += reds[i];

    const float inv = 1.0f / bs;
    union { __nv_bfloat162 b2[2]; uint2 u; } ph, pm;
    bf16 h[4];
#pragma unroll
    for (int j = 0; j < 4; j++) { e[j] *= inv; h[j] = __float2bfloat16(e[j]); }
    ph.b2[0] = __halves2bfloat162(h[0], h[1]);
    ph.b2[1] = __halves2bfloat162(h[2], h[3]);
    pm.b2[0] = __halves2bfloat162(__float2bfloat16(e[0] - __bfloat162float(h[0])),
                                  __float2bfloat16(e[1] - __bfloat162float(h[1])));
    pm.b2[1] = __halves2bfloat162(__float2bfloat16(e[2] - __bfloat162float(h[2])),
                                  __float2bfloat16(e[3] - __bfloat162float(h[3])));
    *(uint2*)(Ph + base + c0) = ph.u;
    *(uint2*)(Pm + base + c0) = pm.u;
}

// ---------------------------------------------------------------------------
__global__ void zero_k(float* __restrict__ p, int n)
{
    int i = blockIdx.x * blockDim.x + threadIdx.x;
    if (i < n) p[i] = 0.f;
}

// out[b,d] = mean_t(res) + (S1[b,:]/T) @ fw2[:,d], res reconstructed hi+mid
__global__ __launch_bounds__(512)
void final_k(const bf16* __restrict__ rh, const bf16* __restrict__ rm,
             const float* __restrict__ S1, const float* __restrict__ fw2,
             float* __restrict__ out)
{
    __shared__ float s1s[FF];
    const int b = blockIdx.x;
    const int d = threadIdx.x;
    for (int i = threadIdx.x; i < FF; i += 512)
        s1s[i] = S1[b * FF + i] * (1.0f / (float)TT);
    __syncthreads();

    float acc = 0.f;
    const long boff = (long)b * TT * DD + d;
#pragma unroll 4
    for (int t = 0; t < TT; t++) {
        long idx = boff + (long)t * DD;
        acc += __bfloat162float(rh[idx]) + __bfloat162float(rm[idx]);
    }
    acc *= 1.0f / (float)TT;

#pragma unroll 4
    for (int f = 0; f < FF; f++) acc += s1s[f] * fw2[(long)f * DD + d];

    out[b * DD + d] = acc;
}

// ---------------------------------------------------------------------------
// Launch
// ---------------------------------------------------------------------------
extern "C" void kernel_launch(void* const* d_in, const int* in_sizes, int n_in,
                              void* d_out, int out_size)
{
    const float* queries = (const float*)d_in[0];
    const float* keys    = (const float*)d_in[1];
    const float* Wq      = (const float*)d_in[2];
    const float* Wk      = (const float*)d_in[3];
    const float* Wv      = (const float*)d_in[4];
    const float* fw1     = (const float*)d_in[5];
    const float* fw2     = (const float*)d_in[6];
    float* out = (float*)d_out;

    bf16 *aqh, *aqm, *akh, *akm, *wqh, *wqm, *wkh, *wkm, *wvh, *wvm, *f1h, *f1m;
    bf16 *qh, *qm, *kh, *km, *vh, *vm, *vth, *vtm, *resh, *resm, *ph, *pm;
    float *s, *S1;
    cudaGetSymbolAddress((void**)&aqh, g_aq_hi);  cudaGetSymbolAddress((void**)&aqm, g_aq_mi);
    cudaGetSymbolAddress((void**)&akh, g_ak_hi);  cudaGetSymbolAddress((void**)&akm, g_ak_mi);
    cudaGetSymbolAddress((void**)&wqh, g_wqt_hi); cudaGetSymbolAddress((void**)&wqm, g_wqt_mi);
    cudaGetSymbolAddress((void**)&wkh, g_wkt_hi); cudaGetSymbolAddress((void**)&wkm, g_wkt_mi);
    cudaGetSymbolAddress((void**)&wvh, g_wvt_hi); cudaGetSymbolAddress((void**)&wvm, g_wvt_mi);
    cudaGetSymbolAddress((void**)&f1h, g_f1t_hi); cudaGetSymbolAddress((void**)&f1m, g_f1t_mi);
    cudaGetSymbolAddress((void**)&qh,  g_q_hi);   cudaGetSymbolAddress((void**)&qm,  g_q_mi);
    cudaGetSymbolAddress((void**)&kh,  g_k_hi);   cudaGetSymbolAddress((void**)&km,  g_k_mi);
    cudaGetSymbolAddress((void**)&vh,  g_v_hi);   cudaGetSymbolAddress((void**)&vm,  g_v_mi);
    cudaGetSymbolAddress((void**)&vth, g_vt_hi);  cudaGetSymbolAddress((void**)&vtm, g_vt_mi);
    cudaGetSymbolAddress((void**)&resh, g_res_hi);cudaGetSymbolAddress((void**)&resm, g_res_mi);
    cudaGetSymbolAddress((void**)&ph,  g_p_hi);   cudaGetSymbolAddress((void**)&pm,  g_p_mi);
    cudaGetSymbolAddress((void**)&s,   g_s);      cudaGetSymbolAddress((void**)&S1,  g_S1);

    // 3 stages * (A pair + B pair) * 40 elems/row * 2B
    const int SMEM128 = 3 * (2 * 128 + 2 * 128) * 40 * 2;   // 122880
    const int SMEM64  = 3 * (2 * 128 + 2 * 64)  * 40 * 2;   // 92160
    cudaFuncSetAttribute(gemm_mma<128, 0>, cudaFuncAttributeMaxDynamicSharedMemorySize, SMEM128);
    cudaFuncSetAttribute(gemm_mma<128, 1>, cudaFuncAttributeMaxDynamicSharedMemorySize, SMEM128);
    cudaFuncSetAttribute(gemm_mma<128, 2>, cudaFuncAttributeMaxDynamicSharedMemorySize, SMEM128);
    cudaFuncSetAttribute(gemm_mma<64, 0>,  cudaFuncAttributeMaxDynamicSharedMemorySize, SMEM64);

    const long TD  = (long)TT * DD;      // 524288
    const long TT2 = (long)TT * TT;      // 1048576

    // 1) input conversions
    cvt_k<<<(MTOT * DD + 255) / 256, 256>>>(queries, aqh, aqm, MTOT * DD);
    cvt_k<<<(MTOT * DD + 255) / 256, 256>>>(keys,    akh, akm, MTOT * DD);
    trcvt_k<<<dim3(DD / 32, DD / 32), dim3(32, 8)>>>(Wq,  wqh, wqm, DD, DD);
    trcvt_k<<<dim3(DD / 32, DD / 32), dim3(32, 8)>>>(Wk,  wkh, wkm, DD, DD);
    trcvt_k<<<dim3(DD / 32, DD / 32), dim3(32, 8)>>>(Wv,  wvh, wvm, DD, DD);
    trcvt_k<<<dim3(FF / 32, DD / 32), dim3(32, 8)>>>(fw1, f1h, f1m, DD, FF);

    // 2) projections: q = queries@Wq, k = keys@Wk, v = k@Wv
    gemm_mma<128, 0><<<dim3(DD / 128, MTOT / 128, 1), 256, SMEM128>>>(
        aqh, aqm, DD, 0, 0,  wqh, wqm, DD, 0, 0,  1.0f, DD, 1,
        qh, qm, DD, 0, 0, nullptr, nullptr, nullptr);
    gemm_mma<128, 0><<<dim3(DD / 128, MTOT / 128, 1), 256, SMEM128>>>(
        akh, akm, DD, 0, 0,  wkh, wkm, DD, 0, 0,  1.0f, DD, 1,
        kh, km, DD, 0, 0, nullptr, nullptr, nullptr);
    gemm_mma<128, 0><<<dim3(DD / 128, MTOT / 128, 1), 256, SMEM128>>>(
        kh, km, DD, 0, 0,  wvh, wvm, DD, 0, 0,  1.0f, DD, 1,
        vh, vm, DD, 0, 0, nullptr, nullptr, nullptr);

    // 3) v transpose per batch: [t,d] -> [d,t]
    transpose_pair_k<<<dim3(TT / 32, DD / 32, BB), dim3(32, 8)>>>(vh, vm, vth, vtm);

    // 4) scores: S[b,h] = (Qh @ Kh^T)/8     z = b*8 + h
    gemm_mma<128, 1><<<dim3(TT / 128, TT / 128, BB * HH), 256, SMEM128>>>(
        qh, qm, DD, TD, DHH,  kh, km, DD, TD, DHH,  0.125f, DHH, HH,
        nullptr, nullptr, TT, (long)HH * TT2, TT2, nullptr, s, nullptr);

    // 5) softmax + diag blind -> P pair
    softmax_diag_k<<<dim3(TT, BB * HH), 256>>>(s, ph, pm);

    // 6) PV + residual: res[b,t,h*64+d] = sum_s P*V + queries
    gemm_mma<64, 0><<<dim3(1, TT / 128, BB * HH), 256, SMEM64>>>(
        ph, pm, TT, (long)HH * TT2, TT2,
        vth, vtm, TT, (long)DD * TT, (long)DHH * TT,
        1.0f, TT, HH,
        resh, resm, DD, TD, DHH, queries, nullptr, nullptr);

    // 7) FFN1: relu + per-batch column sums into S1 (FFN2 folded into final)
    zero_k<<<(BB * FF + 1023) / 1024, 1024>>>(S1, BB * FF);
    gemm_mma<128, 2><<<dim3(FF / 128, MTOT / 128, 1), 256, SMEM128>>>(
        resh, resm, DD, 0, 0,  f1h, f1m, DD, 0, 0,  1.0f, DD, 1,
        nullptr, nullptr, 0, 0, 0, nullptr, nullptr, S1);

    // 8) out = mean_t(res) + (S1/T) @ fw2
    final_k<<<BB, 512>>>(resh, resm, S1, fw2, out);
}

// round 5
// speedup vs baseline: 1.8611x; 1.2223x over previous
#include <cuda_runtime.h>
#include <cuda_bf16.h>
#include <cstdint>

// ---------------------------------------------------------------------------
// Problem constants
// ---------------------------------------------------------------------------
#define BB   16
#define TT   1024
#define DD   512
#define HH   8
#define DHH  64
#define MTOT (BB*TT)        // 16384
#define FF   (4*DD)         // 2048

typedef __nv_bfloat16 bf16;

// ---------------------------------------------------------------------------
// Device scratch (__device__ globals; allocation-free rule)
// ---------------------------------------------------------------------------
__device__ bf16  g_aq_hi[MTOT*DD], g_aq_mi[MTOT*DD];   // queries bf16 pair
__device__ bf16  g_ak_hi[MTOT*DD], g_ak_mi[MTOT*DD];   // keys bf16 pair
__device__ bf16  g_wqt_hi[DD*DD],  g_wqt_mi[DD*DD];    // Wq^T
__device__ bf16  g_wkt_hi[DD*DD],  g_wkt_mi[DD*DD];
__device__ bf16  g_wvt_hi[DD*DD],  g_wvt_mi[DD*DD];
__device__ bf16  g_f1t_hi[FF*DD],  g_f1t_mi[FF*DD];    // fw1^T [2048,512]
__device__ bf16  g_q_hi[MTOT*DD],  g_q_mi[MTOT*DD];
__device__ bf16  g_k_hi[MTOT*DD],  g_k_mi[MTOT*DD];
__device__ bf16  g_v_hi[MTOT*DD],  g_v_mi[MTOT*DD];
__device__ bf16  g_vt_hi[MTOT*DD], g_vt_mi[MTOT*DD];   // per-b [512,1024]
__device__ bf16  g_res_hi[MTOT*DD], g_res_mi[MTOT*DD];
__device__ float g_S1[BB*FF];

// ---------------------------------------------------------------------------
// PTX helpers (all base-PTX, sm_80-era: safe under compute_100 target)
// ---------------------------------------------------------------------------
__device__ __forceinline__ uint32_t smem_u32(const void* p) {
    return (uint32_t)__cvta_generic_to_shared((void*)p);
}
__device__ __forceinline__ void cp16(uint32_t dst, const void* src) {
    asm volatile("cp.async.cg.shared.global [%0], [%1], 16;" :: "r"(dst), "l"(src));
}
#define CP_COMMIT() asm volatile("cp.async.commit_group;" ::: "memory")
#define CP_WAIT2()  asm volatile("cp.async.wait_group 2;"  ::: "memory")
#define CP_WAIT0()  asm volatile("cp.async.wait_group 0;"  ::: "memory")

__device__ __forceinline__ void ldm_x4(uint32_t* r, uint32_t addr) {
    asm volatile("ldmatrix.sync.aligned.m8n8.x4.shared.b16 {%0,%1,%2,%3}, [%4];"
        : "=r"(r[0]), "=r"(r[1]), "=r"(r[2]), "=r"(r[3]) : "r"(addr));
}
__device__ __forceinline__ void ldm_x2(uint32_t* r, uint32_t addr) {
    asm volatile("ldmatrix.sync.aligned.m8n8.x2.shared.b16 {%0,%1}, [%2];"
        : "=r"(r[0]), "=r"(r[1]) : "r"(addr));
}
__device__ __forceinline__ void mma16816(float* c, const uint32_t* a, const uint32_t* b) {
    asm volatile(
        "mma.sync.aligned.m16n8k16.row.col.f32.bf16.bf16.f32 "
        "{%0,%1,%2,%3}, {%4,%5,%6,%7}, {%8,%9}, {%0,%1,%2,%3};"
        : "+f"(c[0]), "+f"(c[1]), "+f"(c[2]), "+f"(c[3])
        : "r"(a[0]), "r"(a[1]), "r"(a[2]), "r"(a[3]), "r"(b[0]), "r"(b[1]));
}
__device__ __forceinline__ uint32_t pack_bf2(float x, float y) {
    __nv_bfloat162 t = __halves2bfloat162(__float2bfloat16(x), __float2bfloat16(y));
    return *(uint32_t*)&t;
}

// ---------------------------------------------------------------------------
// bf16 mma.sync GEMM (unchanged from round 4; validated).
// ---------------------------------------------------------------------------
template<int BN, int EPI>
__global__ __launch_bounds__(256)
void gemm_mma(const bf16* __restrict__ Ahi, const bf16* __restrict__ Ami,
              int ldA, long sAo, long sAi,
              const bf16* __restrict__ Bhi, const bf16* __restrict__ Bmi,
              int ldB, long sBo, long sBi,
              float alpha, int K, int ZI,
              bf16* __restrict__ Chi, bf16* __restrict__ Cmi, int ldc,
              long sCo, long sCi,
              const float* __restrict__ Rres,
              float* __restrict__ Cf,
              float* __restrict__ S1)
{
    constexpr int BM = 128, BK = 32, LDS = 40;
    constexpr int NT = BN / 4;
    constexpr int NF = NT / 8;
    constexpr int MF = 4;
    constexpr int AELEMS = 2 * BM * LDS;
    constexpr int BELEMS = 2 * BN * LDS;
    constexpr int STAGE  = AELEMS + BELEMS;

    extern __shared__ bf16 sm[];
    const int tid = threadIdx.x, lane = tid & 31, wid = tid >> 5;
    const int wm = wid >> 2, wn = wid & 3;
    const int g = lane >> 2, t4 = lane & 3;

    const int z = blockIdx.z, zo = z / ZI, zi = z % ZI;
    const int m0 = blockIdx.y * BM, n0 = blockIdx.x * BN;

    const bf16* Ah = Ahi + (long)zo * sAo + (long)zi * sAi + (long)m0 * ldA;
    const bf16* Am = Ami + (long)zo * sAo + (long)zi * sAi + (long)m0 * ldA;
    const bf16* Bh = Bhi + (long)zo * sBo + (long)zi * sBi + (long)n0 * ldB;
    const bf16* Bm = Bmi + (long)zo * sBo + (long)zi * sBi + (long)n0 * ldB;

    const int NC = K / BK;

    auto load_chunk = [&](int c) {
        if (c < NC) {
            bf16* st = sm + (c % 3) * STAGE;
            const long koff = (long)c * BK;
            for (int i = tid; i < 1024; i += 256) {
                int sel = i >> 9, j = i & 511, r = j >> 2, hh = j & 3;
                const bf16* src = (sel ? Am : Ah) + (long)r * ldA + koff + hh * 8;
                cp16(smem_u32(st + sel * (BM * LDS) + r * LDS + hh * 8), src);
            }
            for (int i = tid; i < BN * 8; i += 256) {
                int sel = i >= BN * 4;
                int j = sel ? i - BN * 4 : i;
                int r = j >> 2, hh = j & 3;
                const bf16* src = (sel ? Bm : Bh) + (long)r * ldB + koff + hh * 8;
                cp16(smem_u32(st + AELEMS + sel * (BN * LDS) + r * LDS + hh * 8), src);
            }
        }
        CP_COMMIT();
    };

    float acc[MF][NF][4];
#pragma unroll
    for (int i = 0; i < MF; i++)
#pragma unroll
        for (int j = 0; j < NF; j++)
#pragma unroll
            for (int e = 0; e < 4; e++) acc[i][j][e] = 0.f;

    load_chunk(0);
    load_chunk(1);

    for (int c = 0; c < NC; c++) {
        load_chunk(c + 2);
        CP_WAIT2();
        __syncthreads();

        bf16* st = sm + (c % 3) * STAGE;
        const uint32_t aH = smem_u32(st);
        const uint32_t aM = smem_u32(st + BM * LDS);
        const uint32_t bH = smem_u32(st + AELEMS);
        const uint32_t bM = smem_u32(st + AELEMS + BN * LDS);

#pragma unroll
        for (int ks = 0; ks < 2; ks++) {
            uint32_t ah[MF][4], am[MF][4], bh[NF][2], bm[NF][2];
            const int acol = ks * 16 + ((lane >> 4) << 3);
            const int ar   = lane & 15;
#pragma unroll
            for (int mf = 0; mf < MF; mf++) {
                int off = (wm * 64 + mf * 16 + ar) * LDS + acol;
                ldm_x4(ah[mf], aH + off * 2);
                ldm_x4(am[mf], aM + off * 2);
            }
            const int bcol = ks * 16 + (((lane >> 3) & 1) << 3);
            const int br   = lane & 7;
#pragma unroll
            for (int nf = 0; nf < NF; nf++) {
                int off = (wn * NT + nf * 8 + br) * LDS + bcol;
                ldm_x2(bh[nf], bH + off * 2);
                ldm_x2(bm[nf], bM + off * 2);
            }
#pragma unroll
            for (int mf = 0; mf < MF; mf++)
#pragma unroll
                for (int nf = 0; nf < NF; nf++) {
                    mma16816(acc[mf][nf], ah[mf], bh[nf]);
                    mma16816(acc[mf][nf], ah[mf], bm[nf]);
                    mma16816(acc[mf][nf], am[mf], bh[nf]);
                }
        }
        __syncthreads();
    }

    if constexpr (EPI == 2) {
        float* cs = (float*)sm;
        if (tid < BN) cs[tid] = 0.f;
        __syncthreads();
#pragma unroll
        for (int nf = 0; nf < NF; nf++) {
            float s0 = 0.f, s1 = 0.f;
#pragma unroll
            for (int mf = 0; mf < MF; mf++) {
                s0 += fmaxf(acc[mf][nf][0], 0.f) + fmaxf(acc[mf][nf][2], 0.f);
                s1 += fmaxf(acc[mf][nf][1], 0.f) + fmaxf(acc[mf][nf][3], 0.f);
            }
            int col = wn * NT + nf * 8 + t4 * 2;
            atomicAdd(&cs[col], s0);
            atomicAdd(&cs[col + 1], s1);
        }
        __syncthreads();
        if (tid < BN)
            atomicAdd(&S1[(m0 / TT) * FF + n0 + tid], cs[tid]);
    } else if constexpr (EPI == 1) {
        float* Cb = Cf + (long)zo * sCo + (long)zi * sCi;
#pragma unroll
        for (int mf = 0; mf < MF; mf++)
#pragma unroll
            for (int nf = 0; nf < NF; nf++) {
                long o0 = (long)(m0 + wm * 64 + mf * 16 + g) * ldc
                        + n0 + wn * NT + nf * 8 + t4 * 2;
                *(float2*)&Cb[o0] =
                    make_float2(alpha * acc[mf][nf][0], alpha * acc[mf][nf][1]);
                *(float2*)&Cb[o0 + 8 * (long)ldc] =
                    make_float2(alpha * acc[mf][nf][2], alpha * acc[mf][nf][3]);
            }
    } else {
        bf16* Ch = Chi + (long)zo * sCo + (long)zi * sCi;
        bf16* Cm = Cmi + (long)zo * sCo + (long)zi * sCi;
        const float* Rb = Rres ? Rres + (long)zo * sCo + (long)zi * sCi : nullptr;
#pragma unroll
        for (int mf = 0; mf < MF; mf++)
#pragma unroll
            for (int nf = 0; nf < NF; nf++) {
#pragma unroll
                for (int half = 0; half < 2; half++) {
                    long o0 = (long)(m0 + wm * 64 + mf * 16 + g + half * 8) * ldc
                            + n0 + wn * NT + nf * 8 + t4 * 2;
                    float v0 = alpha * acc[mf][nf][half * 2 + 0];
                    float v1 = alpha * acc[mf][nf][half * 2 + 1];
                    if (Rb) {
                        float2 r2 = *(const float2*)&Rb[o0];
                        v0 += r2.x; v1 += r2.y;
                    }
                    bf16 h0 = __float2bfloat16(v0);
                    bf16 h1 = __float2bfloat16(v1);
                    __nv_bfloat162 ph = __halves2bfloat162(h0, h1);
                    __nv_bfloat162 pm = __halves2bfloat162(
                        __float2bfloat16(v0 - __bfloat162float(h0)),
                        __float2bfloat16(v1 - __bfloat162float(h1)));
                    *(uint32_t*)&Ch[o0] = *(uint32_t*)&ph;
                    *(uint32_t*)&Cm[o0] = *(uint32_t*)&pm;
                }
            }
    }
}

// ---------------------------------------------------------------------------
// Fused flash attention: S and P never hit global memory.
// Grid (8 q-tiles, 128 b*h). CTA: 256 thr (8 warps x 16 rows), Q tile 128x64.
// Online softmax with diagonal blinding; output res = O + queries (hi/mi pair).
// ---------------------------------------------------------------------------
#define QP 72           // pitch for 64-col tiles (conflict-free ldmatrix)
#define VP 136          // pitch for 128-col V^T tiles

__global__ __launch_bounds__(256, 1)
void flash_attn_k(const bf16* __restrict__ qh_, const bf16* __restrict__ qm_,
                  const bf16* __restrict__ kh_, const bf16* __restrict__ km_,
                  const bf16* __restrict__ vth_, const bf16* __restrict__ vtm_,
                  const float* __restrict__ queries,
                  bf16* __restrict__ resh, bf16* __restrict__ resm)
{
    extern __shared__ bf16 sm[];
    const int tid = threadIdx.x, lane = tid & 31, wid = tid >> 5;
    const int g = lane >> 2, t4 = lane & 3, br = lane & 7;
    const int qt = blockIdx.x, bh = blockIdx.y;
    const int b = bh >> 3, h = bh & 7;
    const int q0 = qt * 128;

    // smem element offsets: Q(hi,mi) | K bufs x2 (hi,mi) | V bufs x2 (hi,mi)
    const int QH = 0, QM = 9216;
    const int KB = 18432;          // + buf*18432 ; KM = +9216
    const int VB = 55296;          // + buf*17408 ; VM = +8704

    auto stageK = [&](int kt) {
        const int kb = KB + (kt & 1) * 18432;
        for (int i = tid; i < 2048; i += 256) {
            int sel = i >> 10, j = i & 1023, r = j >> 3, c = j & 7;
            const bf16* src = (sel ? km_ : kh_)
                + ((long)(b * TT + kt * 128 + r)) * DD + h * DHH + c * 8;
            cp16(smem_u32(sm + kb + sel * 9216 + r * QP + c * 8), src);
        }
        const int vb = VB + (kt & 1) * 17408;
        for (int i = tid; i < 2048; i += 256) {
            int sel = i >> 10, j = i & 1023, r = j >> 4, c = j & 15;
            const bf16* src = (sel ? vtm_ : vth_)
                + ((long)(b * DD + h * DHH + r)) * TT + kt * 128 + c * 8;
            cp16(smem_u32(sm + vb + sel * 8704 + r * VP + c * 8), src);
        }
    };

    // stage Q + tile 0
    for (int i = tid; i < 2048; i += 256) {
        int sel = i >> 10, j = i & 1023, r = j >> 3, c = j & 7;
        const bf16* src = (sel ? qm_ : qh_)
            + ((long)(b * TT + q0 + r)) * DD + h * DHH + c * 8;
        cp16(smem_u32(sm + (sel ? QM : QH) + r * QP + c * 8), src);
    }
    stageK(0);
    CP_COMMIT();
    CP_WAIT0();
    __syncthreads();

    // preload Q fragments (held all loop)
    uint32_t qhf[4][4], qmf[4][4];
    {
        const int ar = lane & 15;
#pragma unroll
        for (int ks = 0; ks < 4; ks++) {
            int acol = ks * 16 + ((lane >> 4) << 3);
            int off = (wid * 16 + ar) * QP + acol;
            ldm_x4(qhf[ks], smem_u32(sm + QH) + off * 2);
            ldm_x4(qmf[ks], smem_u32(sm + QM) + off * 2);
        }
    }

    float o[8][4];
#pragma unroll
    for (int i = 0; i < 8; i++)
#pragma unroll
        for (int e = 0; e < 4; e++) o[i][e] = 0.f;
    float m_lo = -1e30f, m_hi = -1e30f, l_lo = 0.f, l_hi = 0.f;

    const int bcol8 = ((lane >> 3) & 1) << 3;

    for (int kt = 0; kt < 8; kt++) {
        if (kt > 0) { CP_WAIT0(); }
        __syncthreads();
        if (kt + 1 < 8) { stageK(kt + 1); CP_COMMIT(); }

        const uint32_t kH = smem_u32(sm + KB + (kt & 1) * 18432);
        const uint32_t kM = kH + 9216 * 2;
        const uint32_t vH = smem_u32(sm + VB + (kt & 1) * 17408);
        const uint32_t vM = vH + 8704 * 2;

        // ---- S = Q K^T (3-pass), 16 n-frags of 8 cols ----
        float s[16][4];
#pragma unroll
        for (int nf = 0; nf < 16; nf++) {
#pragma unroll
            for (int e = 0; e < 4; e++) s[nf][e] = 0.f;
#pragma unroll
            for (int ks = 0; ks < 4; ks++) {
                uint32_t bh2[2], bm2[2];
                int off = (nf * 8 + br) * QP + ks * 16 + bcol8;
                ldm_x2(bh2, kH + off * 2);
                ldm_x2(bm2, kM + off * 2);
                mma16816(s[nf], qhf[ks], bh2);
                mma16816(s[nf], qhf[ks], bm2);
                mma16816(s[nf], qmf[ks], bh2);
            }
        }

        // scale + diagonal blinding
#pragma unroll
        for (int nf = 0; nf < 16; nf++)
#pragma unroll
            for (int e = 0; e < 4; e++) s[nf][e] *= 0.125f;
        if (kt == qt) {
#pragma unroll
            for (int nf = 0; nf < 16; nf++)
#pragma unroll
                for (int e = 0; e < 4; e++) {
                    int row = wid * 16 + g + ((e >> 1) << 3);
                    int col = nf * 8 + t4 * 2 + (e & 1);
                    if (row == col) s[nf][e] = -1e30f;
                }
        }

        // ---- online softmax update ----
        float mn_lo = -1e30f, mn_hi = -1e30f;
#pragma unroll
        for (int nf = 0; nf < 16; nf++) {
            mn_lo = fmaxf(mn_lo, fmaxf(s[nf][0], s[nf][1]));
            mn_hi = fmaxf(mn_hi, fmaxf(s[nf][2], s[nf][3]));
        }
        mn_lo = fmaxf(mn_lo, __shfl_xor_sync(0xffffffffu, mn_lo, 1));
        mn_lo = fmaxf(mn_lo, __shfl_xor_sync(0xffffffffu, mn_lo, 2));
        mn_hi = fmaxf(mn_hi, __shfl_xor_sync(0xffffffffu, mn_hi, 1));
        mn_hi = fmaxf(mn_hi, __shfl_xor_sync(0xffffffffu, mn_hi, 2));

        float mc_lo = fmaxf(m_lo, mn_lo), mc_hi = fmaxf(m_hi, mn_hi);
        float sc_lo = __expf(m_lo - mc_lo), sc_hi = __expf(m_hi - mc_hi);
        l_lo *= sc_lo; l_hi *= sc_hi;
#pragma unroll
        for (int nf = 0; nf < 8; nf++) {
            o[nf][0] *= sc_lo; o[nf][1] *= sc_lo;
            o[nf][2] *= sc_hi; o[nf][3] *= sc_hi;
        }
#pragma unroll
        for (int nf = 0; nf < 16; nf++) {
            s[nf][0] = __expf(s[nf][0] - mc_lo);
            s[nf][1] = __expf(s[nf][1] - mc_lo);
            s[nf][2] = __expf(s[nf][2] - mc_hi);
            s[nf][3] = __expf(s[nf][3] - mc_hi);
            l_lo += s[nf][0] + s[nf][1];
            l_hi += s[nf][2] + s[nf][3];
        }
        m_lo = mc_lo; m_hi = mc_hi;

        // ---- O += P V (3-pass); S-acc layout == A-frag layout ----
#pragma unroll
        for (int ks = 0; ks < 8; ks++) {
            uint32_t pa[4], pb[4];
            pa[0] = pack_bf2(s[2*ks][0],   s[2*ks][1]);
            pa[1] = pack_bf2(s[2*ks][2],   s[2*ks][3]);
            pa[2] = pack_bf2(s[2*ks+1][0], s[2*ks+1][1]);
            pa[3] = pack_bf2(s[2*ks+1][2], s[2*ks+1][3]);
            // mid = p - bf16(p)
            {
                __nv_bfloat162 t;
#pragma unroll
                for (int q = 0; q < 4; q++) {
                    float x0 = s[2*ks + (q >> 1)][(q & 1) * 2 + 0];
                    float x1 = s[2*ks + (q >> 1)][(q & 1) * 2 + 1];
                    // recompute hi to get residual
                    __nv_bfloat162* ph = (__nv_bfloat162*)&pa[q];
                    t = __halves2bfloat162(
                        __float2bfloat16(x0 - __bfloat162float(__low2bfloat16(*ph))),
                        __float2bfloat16(x1 - __bfloat162float(__high2bfloat16(*ph))));
                    pb[q] = *(uint32_t*)&t;
                }
            }
#pragma unroll
            for (int nf = 0; nf < 8; nf++) {
                uint32_t vh2[2], vm2[2];
                int off = (nf * 8 + br) * VP + ks * 16 + bcol8;
                ldm_x2(vh2, vH + off * 2);
                ldm_x2(vm2, vM + off * 2);
                mma16816(o[nf], pa, vh2);
                mma16816(o[nf], pa, vm2);
                mma16816(o[nf], pb, vh2);
            }
        }
        __syncthreads();
    }

    // ---- epilogue: O/l + queries residual -> res pair ----
    l_lo += __shfl_xor_sync(0xffffffffu, l_lo, 1);
    l_lo += __shfl_xor_sync(0xffffffffu, l_lo, 2);
    l_hi += __shfl_xor_sync(0xffffffffu, l_hi, 1);
    l_hi += __shfl_xor_sync(0xffffffffu, l_hi, 2);
    const float inv_lo = 1.0f / l_lo, inv_hi = 1.0f / l_hi;

#pragma unroll
    for (int nf = 0; nf < 8; nf++) {
#pragma unroll
        for (int half = 0; half < 2; half++) {
            int row = q0 + wid * 16 + g + half * 8;
            int col = h * DHH + nf * 8 + t4 * 2;
            long idx = (long)(b * TT + row) * DD + col;
            float inv = half ? inv_hi : inv_lo;
            float2 r2 = *(const float2*)&queries[idx];
            float v0 = o[nf][half * 2 + 0] * inv + r2.x;
            float v1 = o[nf][half * 2 + 1] * inv + r2.y;
            bf16 h0 = __float2bfloat16(v0);
            bf16 h1 = __float2bfloat16(v1);
            __nv_bfloat162 ph = __halves2bfloat162(h0, h1);
            __nv_bfloat162 pm = __halves2bfloat162(
                __float2bfloat16(v0 - __bfloat162float(h0)),
                __float2bfloat16(v1 - __bfloat162float(h1)));
            *(uint32_t*)&resh[idx] = *(uint32_t*)&ph;
            *(uint32_t*)&resm[idx] = *(uint32_t*)&pm;
        }
    }
}

// ---------------------------------------------------------------------------
__global__ void cvt_k(const float* __restrict__ in, bf16* __restrict__ oh,
                      bf16* __restrict__ om, int n)
{
    int i = blockIdx.x * blockDim.x + threadIdx.x;
    if (i < n) {
        float x = in[i];
        bf16 h = __float2bfloat16(x);
        oh[i] = h;
        om[i] = __float2bfloat16(x - __bfloat162float(h));
    }
}

__global__ void trcvt_k(const float* __restrict__ in, bf16* __restrict__ oh,
                        bf16* __restrict__ om, int R, int C)
{
    __shared__ float tile[32][33];
    int r0 = blockIdx.y * 32, c0 = blockIdx.x * 32;
    for (int i = threadIdx.y; i < 32; i += 8)
        tile[i][threadIdx.x] = in[(long)(r0 + i) * C + c0 + threadIdx.x];
    __syncthreads();
    for (int i = threadIdx.y; i < 32; i += 8) {
        float x = tile[threadIdx.x][i];
        bf16 h = __float2bfloat16(x);
        long dst = (long)(c0 + i) * R + r0 + threadIdx.x;
        oh[dst] = h;
        om[dst] = __float2bfloat16(x - __bfloat162float(h));
    }
}

__global__ void transpose_pair_k(const bf16* __restrict__ vh, const bf16* __restrict__ vm,
                                 bf16* __restrict__ oh, bf16* __restrict__ om)
{
    __shared__ bf16 th[32][33], tm[32][33];
    int b = blockIdx.z;
    int t0 = blockIdx.x * 32, d0 = blockIdx.y * 32;
    for (int i = threadIdx.y; i < 32; i += 8) {
        long src = ((long)(b * TT + t0 + i)) * DD + d0 + threadIdx.x;
        th[i][threadIdx.x] = vh[src];
        tm[i][threadIdx.x] = vm[src];
    }
    __syncthreads();
    for (int i = threadIdx.y; i < 32; i += 8) {
        long dst = (long)b * DD * TT + (long)(d0 + i) * TT + t0 + threadIdx.x;
        oh[dst] = th[threadIdx.x][i];
        om[dst] = tm[threadIdx.x][i];
    }
}

__global__ void zero_k(float* __restrict__ p, int n)
{
    int i = blockIdx.x * blockDim.x + threadIdx.x;
    if (i < n) p[i] = 0.f;
}

__global__ __launch_bounds__(512)
void final_k(const bf16* __restrict__ rh, const bf16* __restrict__ rm,
             const float* __restrict__ S1, const float* __restrict__ fw2,
             float* __restrict__ out)
{
    __shared__ float s1s[FF];
    const int b = blockIdx.x;
    const int d = threadIdx.x;
    for (int i = threadIdx.x; i < FF; i += 512)
        s1s[i] = S1[b * FF + i] * (1.0f / (float)TT);
    __syncthreads();

    float acc = 0.f;
    const long boff = (long)b * TT * DD + d;
#pragma unroll 4
    for (int t = 0; t < TT; t++) {
        long idx = boff + (long)t * DD;
        acc += __bfloat162float(rh[idx]) + __bfloat162float(rm[idx]);
    }
    acc *= 1.0f / (float)TT;

#pragma unroll 4
    for (int f = 0; f < FF; f++) acc += s1s[f] * fw2[(long)f * DD + d];

    out[b * DD + d] = acc;
}

// ---------------------------------------------------------------------------
// Launch
// ---------------------------------------------------------------------------
extern "C" void kernel_launch(void* const* d_in, const int* in_sizes, int n_in,
                              void* d_out, int out_size)
{
    const float* queries = (const float*)d_in[0];
    const float* keys    = (const float*)d_in[1];
    const float* Wq      = (const float*)d_in[2];
    const float* Wk      = (const float*)d_in[3];
    const float* Wv      = (const float*)d_in[4];
    const float* fw1     = (const float*)d_in[5];
    const float* fw2     = (const float*)d_in[6];
    float* out = (float*)d_out;

    bf16 *aqh, *aqm, *akh, *akm, *wqh, *wqm, *wkh, *wkm, *wvh, *wvm, *f1h, *f1m;
    bf16 *qh, *qm, *kh, *km, *vh, *vm, *vth, *vtm, *resh, *resm;
    float *S1;
    cudaGetSymbolAddress((void**)&aqh, g_aq_hi);  cudaGetSymbolAddress((void**)&aqm, g_aq_mi);
    cudaGetSymbolAddress((void**)&akh, g_ak_hi);  cudaGetSymbolAddress((void**)&akm, g_ak_mi);
    cudaGetSymbolAddress((void**)&wqh, g_wqt_hi); cudaGetSymbolAddress((void**)&wqm, g_wqt_mi);
    cudaGetSymbolAddress((void**)&wkh, g_wkt_hi); cudaGetSymbolAddress((void**)&wkm, g_wkt_mi);
    cudaGetSymbolAddress((void**)&wvh, g_wvt_hi); cudaGetSymbolAddress((void**)&wvm, g_wvt_mi);
    cudaGetSymbolAddress((void**)&f1h, g_f1t_hi); cudaGetSymbolAddress((void**)&f1m, g_f1t_mi);
    cudaGetSymbolAddress((void**)&qh,  g_q_hi);   cudaGetSymbolAddress((void**)&qm,  g_q_mi);
    cudaGetSymbolAddress((void**)&kh,  g_k_hi);   cudaGetSymbolAddress((void**)&km,  g_k_mi);
    cudaGetSymbolAddress((void**)&vh,  g_v_hi);   cudaGetSymbolAddress((void**)&vm,  g_v_mi);
    cudaGetSymbolAddress((void**)&vth, g_vt_hi);  cudaGetSymbolAddress((void**)&vtm, g_vt_mi);
    cudaGetSymbolAddress((void**)&resh, g_res_hi);cudaGetSymbolAddress((void**)&resm, g_res_mi);
    cudaGetSymbolAddress((void**)&S1,  g_S1);

    const int SMEM128 = 3 * (2 * 128 + 2 * 128) * 40 * 2;   // 122880
    const int SMEMFA  = (18432 + 2 * 18432 + 2 * 17408) * 2; // 180224
    cudaFuncSetAttribute(gemm_mma<128, 0>, cudaFuncAttributeMaxDynamicSharedMemorySize, SMEM128);
    cudaFuncSetAttribute(gemm_mma<128, 2>, cudaFuncAttributeMaxDynamicSharedMemorySize, SMEM128);
    cudaFuncSetAttribute(flash_attn_k, cudaFuncAttributeMaxDynamicSharedMemorySize, SMEMFA);

    // 1) input conversions
    cvt_k<<<(MTOT * DD + 255) / 256, 256>>>(queries, aqh, aqm, MTOT * DD);
    cvt_k<<<(MTOT * DD + 255) / 256, 256>>>(keys,    akh, akm, MTOT * DD);
    trcvt_k<<<dim3(DD / 32, DD / 32), dim3(32, 8)>>>(Wq,  wqh, wqm, DD, DD);
    trcvt_k<<<dim3(DD / 32, DD / 32), dim3(32, 8)>>>(Wk,  wkh, wkm, DD, DD);
    trcvt_k<<<dim3(DD / 32, DD / 32), dim3(32, 8)>>>(Wv,  wvh, wvm, DD, DD);
    trcvt_k<<<dim3(FF / 32, DD / 32), dim3(32, 8)>>>(fw1, f1h, f1m, DD, FF);

    // 2) projections: q = queries@Wq, k = keys@Wk, v = k@Wv
    gemm_mma<128, 0><<<dim3(DD / 128, MTOT / 128, 1), 256, SMEM128>>>(
        aqh, aqm, DD, 0, 0,  wqh, wqm, DD, 0, 0,  1.0f, DD, 1,
        qh, qm, DD, 0, 0, nullptr, nullptr, nullptr);
    gemm_mma<128, 0><<<dim3(DD / 128, MTOT / 128, 1), 256, SMEM128>>>(
        akh, akm, DD, 0, 0,  wkh, wkm, DD, 0, 0,  1.0f, DD, 1,
        kh, km, DD, 0, 0, nullptr, nullptr, nullptr);
    gemm_mma<128, 0><<<dim3(DD / 128, MTOT / 128, 1), 256, SMEM128>>>(
        kh, km, DD, 0, 0,  wvh, wvm, DD, 0, 0,  1.0f, DD, 1,
        vh, vm, DD, 0, 0, nullptr, nullptr, nullptr);

    // 3) v transpose per batch: [t,d] -> [d,t]
    transpose_pair_k<<<dim3(TT / 32, DD / 32, BB), dim3(32, 8)>>>(vh, vm, vth, vtm);

    // 4+5+6) fused flash attention + residual
    flash_attn_k<<<dim3(TT / 128, BB * HH), 256, SMEMFA>>>(
        qh, qm, kh, km, vth, vtm, queries, resh, resm);

    // 7) FFN1: relu + per-batch column sums into S1 (FFN2 folded into final)
    zero_k<<<(BB * FF + 1023) / 1024, 1024>>>(S1, BB * FF);
    gemm_mma<128, 2><<<dim3(FF / 128, MTOT / 128, 1), 256, SMEM128>>>(
        resh, resm, DD, 0, 0,  f1h, f1m, DD, 0, 0,  1.0f, DD, 1,
        nullptr, nullptr, 0, 0, 0, nullptr, nullptr, S1);

    // 8) out = mean_t(res) + (S1/T) @ fw2
    final_k<<<BB, 512>>>(resh, resm, S1, fw2, out);
}

// round 6
// speedup vs baseline: 3.4726x; 1.8659x over previous
#include <cuda_runtime.h>
#include <cuda_fp16.h>
#include <cstdint>

// ---------------------------------------------------------------------------
// Problem constants
// ---------------------------------------------------------------------------
#define BB   16
#define TT   1024
#define DD   512
#define HH   8
#define DHH  64
#define MTOT (BB*TT)        // 16384
#define FF   (4*DD)         // 2048

typedef __half h16;

// ---------------------------------------------------------------------------
// Device scratch (__device__ globals; allocation-free rule)
// ---------------------------------------------------------------------------
__device__ h16  g_aq [MTOT*DD];     // queries fp16
__device__ h16  g_ak [MTOT*DD];     // keys fp16
__device__ h16  g_wqt[DD*DD];       // Wq^T
__device__ h16  g_wkt[DD*DD];
__device__ h16  g_wvt[DD*DD];
__device__ h16  g_f1t[FF*DD];       // fw1^T [2048,512]
__device__ h16  g_q  [MTOT*DD];
__device__ h16  g_k  [MTOT*DD];
__device__ h16  g_v  [MTOT*DD];     // [b*T+t][512]
__device__ h16  g_res[MTOT*DD];
__device__ float g_S1[BB*FF];

// ---------------------------------------------------------------------------
// PTX helpers (all base-PTX, sm_80-era: safe under compute_100 target)
// ---------------------------------------------------------------------------
__device__ __forceinline__ uint32_t smem_u32(const void* p) {
    return (uint32_t)__cvta_generic_to_shared((void*)p);
}
__device__ __forceinline__ void cp16(uint32_t dst, const void* src) {
    asm volatile("cp.async.cg.shared.global [%0], [%1], 16;" :: "r"(dst), "l"(src));
}
#define CP_COMMIT() asm volatile("cp.async.commit_group;" ::: "memory")
#define CP_WAIT2()  asm volatile("cp.async.wait_group 2;"  ::: "memory")
#define CP_WAIT0()  asm volatile("cp.async.wait_group 0;"  ::: "memory")

__device__ __forceinline__ void ldm_x4(uint32_t* r, uint32_t addr) {
    asm volatile("ldmatrix.sync.aligned.m8n8.x4.shared.b16 {%0,%1,%2,%3}, [%4];"
        : "=r"(r[0]), "=r"(r[1]), "=r"(r[2]), "=r"(r[3]) : "r"(addr));
}
__device__ __forceinline__ void ldm_x2(uint32_t* r, uint32_t addr) {
    asm volatile("ldmatrix.sync.aligned.m8n8.x2.shared.b16 {%0,%1}, [%2];"
        : "=r"(r[0]), "=r"(r[1]) : "r"(addr));
}
__device__ __forceinline__ void ldm_x2_trans(uint32_t* r, uint32_t addr) {
    asm volatile("ldmatrix.sync.aligned.m8n8.x2.trans.shared.b16 {%0,%1}, [%2];"
        : "=r"(r[0]), "=r"(r[1]) : "r"(addr));
}
__device__ __forceinline__ void mma16816(float* c, const uint32_t* a, const uint32_t* b) {
    asm volatile(
        "mma.sync.aligned.m16n8k16.row.col.f32.f16.f16.f32 "
        "{%0,%1,%2,%3}, {%4,%5,%6,%7}, {%8,%9}, {%0,%1,%2,%3};"
        : "+f"(c[0]), "+f"(c[1]), "+f"(c[2]), "+f"(c[3])
        : "r"(a[0]), "r"(a[1]), "r"(a[2]), "r"(a[3]), "r"(b[0]), "r"(b[1]));
}
__device__ __forceinline__ uint32_t pack_h2(float x, float y) {
    __half2 t = __floats2half2_rn(x, y);
    return *(uint32_t*)&t;
}

// ---------------------------------------------------------------------------
// fp16 mma.sync GEMM (single pass).  D[m][n] = sum_k A[m][k]*B[n][k].
// A [M,K] row-major, B [N,K] n-major. CTA tile 128 x BN, BK=64, 8 warps (2x4),
// 3-stage cp.async pipeline, 2 CTAs/SM.
// EPI 0: C = alpha*D (+R residual f32) -> fp16
// EPI 2: relu(D) column sums atomically into S1[b*FF + n]
// ---------------------------------------------------------------------------
template<int BN, int EPI>
__global__ __launch_bounds__(256, 2)
void gemm_mma(const h16* __restrict__ A_, int ldA, long sAo, long sAi,
              const h16* __restrict__ B_, int ldB, long sBo, long sBi,
              float alpha, int K, int ZI,
              h16* __restrict__ C_, int ldc, long sCo, long sCi,
              const float* __restrict__ Rres,
              float* __restrict__ S1)
{
    constexpr int BM = 128, LDS = 72;              // 144B pitch, conflict-free
    constexpr int NT = BN / 4;
    constexpr int NF = NT / 8;
    constexpr int MF = 4;
    constexpr int STAGE = (BM + BN) * LDS;

    extern __shared__ h16 sm[];
    const int tid = threadIdx.x, lane = tid & 31, wid = tid >> 5;
    const int wm = wid >> 2, wn = wid & 3;
    const int g = lane >> 2, t4 = lane & 3;

    const int z = blockIdx.z, zo = z / ZI, zi = z % ZI;
    const int m0 = blockIdx.y * BM, n0 = blockIdx.x * BN;

    const h16* Ab = A_ + (long)zo * sAo + (long)zi * sAi + (long)m0 * ldA;
    const h16* Bb = B_ + (long)zo * sBo + (long)zi * sBi + (long)n0 * ldB;

    const int NC = K / 64;

    auto load_chunk = [&](int c) {
        if (c < NC) {
            h16* st = sm + (c % 3) * STAGE;
            const long koff = (long)c * 64;
            for (int i = tid; i < BM * 8; i += 256) {
                int r = i >> 3, hh = i & 7;
                cp16(smem_u32(st + r * LDS + hh * 8), Ab + (long)r * ldA + koff + hh * 8);
            }
            for (int i = tid; i < BN * 8; i += 256) {
                int r = i >> 3, hh = i & 7;
                cp16(smem_u32(st + BM * LDS + r * LDS + hh * 8),
                     Bb + (long)r * ldB + koff + hh * 8);
            }
        }
        CP_COMMIT();
    };

    float acc[MF][NF][4];
#pragma unroll
    for (int i = 0; i < MF; i++)
#pragma unroll
        for (int j = 0; j < NF; j++)
#pragma unroll
            for (int e = 0; e < 4; e++) acc[i][j][e] = 0.f;

    load_chunk(0);
    load_chunk(1);

    const int ar = lane & 15;
    const int ac8 = (lane >> 4) << 3;
    const int br = lane & 7;
    const int bc8 = ((lane >> 3) & 1) << 3;

    for (int c = 0; c < NC; c++) {
        load_chunk(c + 2);
        CP_WAIT2();
        __syncthreads();

        h16* st = sm + (c % 3) * STAGE;
        const uint32_t aS = smem_u32(st);
        const uint32_t bS = smem_u32(st + BM * LDS);

#pragma unroll
        for (int ks = 0; ks < 4; ks++) {
            uint32_t ah[MF][4], bh[NF][2];
            const int acol = ks * 16 + ac8;
#pragma unroll
            for (int mf = 0; mf < MF; mf++)
                ldm_x4(ah[mf], aS + ((wm * 64 + mf * 16 + ar) * LDS + acol) * 2);
            const int bcol = ks * 16 + bc8;
#pragma unroll
            for (int nf = 0; nf < NF; nf++)
                ldm_x2(bh[nf], bS + ((wn * NT + nf * 8 + br) * LDS + bcol) * 2);
#pragma unroll
            for (int mf = 0; mf < MF; mf++)
#pragma unroll
                for (int nf = 0; nf < NF; nf++)
                    mma16816(acc[mf][nf], ah[mf], bh[nf]);
        }
        __syncthreads();
    }

    if constexpr (EPI == 2) {
        float* cs = (float*)sm;
        if (tid < BN) cs[tid] = 0.f;
        __syncthreads();
#pragma unroll
        for (int nf = 0; nf < NF; nf++) {
            float s0 = 0.f, s1 = 0.f;
#pragma unroll
            for (int mf = 0; mf < MF; mf++) {
                s0 += fmaxf(acc[mf][nf][0], 0.f) + fmaxf(acc[mf][nf][2], 0.f);
                s1 += fmaxf(acc[mf][nf][1], 0.f) + fmaxf(acc[mf][nf][3], 0.f);
            }
            int col = wn * NT + nf * 8 + t4 * 2;
            atomicAdd(&cs[col], s0);
            atomicAdd(&cs[col + 1], s1);
        }
        __syncthreads();
        if (tid < BN)
            atomicAdd(&S1[(m0 / TT) * FF + n0 + tid], cs[tid]);
    } else {
        h16* Cb = C_ + (long)zo * sCo + (long)zi * sCi;
        const float* Rb = Rres ? Rres + (long)zo * sCo + (long)zi * sCi : nullptr;
#pragma unroll
        for (int mf = 0; mf < MF; mf++)
#pragma unroll
            for (int nf = 0; nf < NF; nf++) {
#pragma unroll
                for (int half = 0; half < 2; half++) {
                    long o0 = (long)(m0 + wm * 64 + mf * 16 + g + half * 8) * ldc
                            + n0 + wn * NT + nf * 8 + t4 * 2;
                    float v0 = alpha * acc[mf][nf][half * 2 + 0];
                    float v1 = alpha * acc[mf][nf][half * 2 + 1];
                    if (Rb) {
                        float2 r2 = *(const float2*)&Rb[o0];
                        v0 += r2.x; v1 += r2.y;
                    }
                    *(uint32_t*)&Cb[o0] = pack_h2(v0, v1);
                }
            }
    }
}

// ---------------------------------------------------------------------------
// Fused flash attention, fp16 single-pass. Grid (8 q-tiles, 128 b*h).
// 256 thr (8 warps x 16 rows), Q tile 128x64. V consumed from [t,d] layout
// via ldmatrix.trans (no pre-transpose). Online softmax + diag blinding.
// Output res = O + queries (fp16).
// ---------------------------------------------------------------------------
#define QP 72           // pitch (halfs) for 64-col tiles; 144B rows

__global__ __launch_bounds__(256, 1)
void flash_attn_k(const h16* __restrict__ q_, const h16* __restrict__ k_,
                  const h16* __restrict__ v_,
                  const float* __restrict__ queries,
                  h16* __restrict__ res_)
{
    extern __shared__ h16 sm[];
    const int tid = threadIdx.x, lane = tid & 31, wid = tid >> 5;
    const int g = lane >> 2, t4 = lane & 3, br = lane & 7;
    const int qt = blockIdx.x, bh = blockIdx.y;
    const int b = bh >> 3, h = bh & 7;
    const int q0 = qt * 128;

    // smem (halfs): Q | K bufs x2 | V bufs x2, each 128x72
    const int TILE = 128 * QP;                 // 9216
    const int QH = 0, KB = TILE, VB = 3 * TILE;

    auto stageKV = [&](int kt) {
        const int kb = KB + (kt & 1) * TILE;
        const int vb = VB + (kt & 1) * TILE;
        for (int i = tid; i < 2048; i += 256) {
            int sel = i >> 10, j = i & 1023, r = j >> 3, c = j & 7;
            const h16* src = (sel ? v_ : k_)
                + ((long)(b * TT + kt * 128 + r)) * DD + h * DHH + c * 8;
            cp16(smem_u32(sm + (sel ? vb : kb) + r * QP + c * 8), src);
        }
    };

    // stage Q + tile 0
    for (int i = tid; i < 1024; i += 256) {
        int r = i >> 3, c = i & 7;
        cp16(smem_u32(sm + QH + r * QP + c * 8),
             q_ + ((long)(b * TT + q0 + r)) * DD + h * DHH + c * 8);
    }
    stageKV(0);
    CP_COMMIT();
    CP_WAIT0();
    __syncthreads();

    // preload Q fragments (held all loop)
    uint32_t qf[4][4];
    {
        const int ar = lane & 15;
#pragma unroll
        for (int ks = 0; ks < 4; ks++) {
            int acol = ks * 16 + ((lane >> 4) << 3);
            ldm_x4(qf[ks], smem_u32(sm + QH) + ((wid * 16 + ar) * QP + acol) * 2);
        }
    }

    float o[8][4];
#pragma unroll
    for (int i = 0; i < 8; i++)
#pragma unroll
        for (int e = 0; e < 4; e++) o[i][e] = 0.f;
    float m_lo = -1e30f, m_hi = -1e30f, l_lo = 0.f, l_hi = 0.f;

    const int bc8 = ((lane >> 3) & 1) << 3;
    // trans-ldmatrix row index within V tile (lanes 0-15 meaningful)
    const int vrow = ((lane >> 3) & 1) * 8 + (lane & 7);

    for (int kt = 0; kt < 8; kt++) {
        if (kt > 0) { CP_WAIT0(); }
        __syncthreads();
        if (kt + 1 < 8) { stageKV(kt + 1); CP_COMMIT(); }

        const uint32_t kS = smem_u32(sm + KB + (kt & 1) * TILE);
        const uint32_t vS = smem_u32(sm + VB + (kt & 1) * TILE);

        // ---- S = Q K^T, 16 n-frags of 8 cols ----
        float s[16][4];
#pragma unroll
        for (int nf = 0; nf < 16; nf++) {
#pragma unroll
            for (int e = 0; e < 4; e++) s[nf][e] = 0.f;
#pragma unroll
            for (int ks = 0; ks < 4; ks++) {
                uint32_t bh2[2];
                ldm_x2(bh2, kS + ((nf * 8 + br) * QP + ks * 16 + bc8) * 2);
                mma16816(s[nf], qf[ks], bh2);
            }
        }

        // scale + diagonal blinding
#pragma unroll
        for (int nf = 0; nf < 16; nf++)
#pragma unroll
            for (int e = 0; e < 4; e++) s[nf][e] *= 0.125f;
        if (kt == qt) {
#pragma unroll
            for (int nf = 0; nf < 16; nf++)
#pragma unroll
                for (int e = 0; e < 4; e++) {
                    int row = wid * 16 + g + ((e >> 1) << 3);
                    int col = nf * 8 + t4 * 2 + (e & 1);
                    if (row == col) s[nf][e] = -1e30f;
                }
        }

        // ---- online softmax update ----
        float mn_lo = -1e30f, mn_hi = -1e30f;
#pragma unroll
        for (int nf = 0; nf < 16; nf++) {
            mn_lo = fmaxf(mn_lo, fmaxf(s[nf][0], s[nf][1]));
            mn_hi = fmaxf(mn_hi, fmaxf(s[nf][2], s[nf][3]));
        }
        mn_lo = fmaxf(mn_lo, __shfl_xor_sync(0xffffffffu, mn_lo, 1));
        mn_lo = fmaxf(mn_lo, __shfl_xor_sync(0xffffffffu, mn_lo, 2));
        mn_hi = fmaxf(mn_hi, __shfl_xor_sync(0xffffffffu, mn_hi, 1));
        mn_hi = fmaxf(mn_hi, __shfl_xor_sync(0xffffffffu, mn_hi, 2));

        float mc_lo = fmaxf(m_lo, mn_lo), mc_hi = fmaxf(m_hi, mn_hi);
        float sc_lo = __expf(m_lo - mc_lo), sc_hi = __expf(m_hi - mc_hi);
        l_lo *= sc_lo; l_hi *= sc_hi;
#pragma unroll
        for (int nf = 0; nf < 8; nf++) {
            o[nf][0] *= sc_lo; o[nf][1] *= sc_lo;
            o[nf][2] *= sc_hi; o[nf][3] *= sc_hi;
        }
#pragma unroll
        for (int nf = 0; nf < 16; nf++) {
            s[nf][0] = __expf(s[nf][0] - mc_lo);
            s[nf][1] = __expf(s[nf][1] - mc_lo);
            s[nf][2] = __expf(s[nf][2] - mc_hi);
            s[nf][3] = __expf(s[nf][3] - mc_hi);
            l_lo += s[nf][0] + s[nf][1];
            l_hi += s[nf][2] + s[nf][3];
        }
        m_lo = mc_lo; m_hi = mc_hi;

        // ---- O += P V ; S-acc layout == A-frag layout; V via ldmatrix.trans ----
#pragma unroll
        for (int ks = 0; ks < 8; ks++) {
            uint32_t pa[4];
            pa[0] = pack_h2(s[2*ks][0],   s[2*ks][1]);
            pa[1] = pack_h2(s[2*ks][2],   s[2*ks][3]);
            pa[2] = pack_h2(s[2*ks+1][0], s[2*ks+1][1]);
            pa[3] = pack_h2(s[2*ks+1][2], s[2*ks+1][3]);
#pragma unroll
            for (int nf = 0; nf < 8; nf++) {
                uint32_t vb2[2];
                ldm_x2_trans(vb2, vS + ((ks * 16 + vrow) * QP + nf * 8) * 2);
                mma16816(o[nf], pa, vb2);
            }
        }
        __syncthreads();
    }

    // ---- epilogue: O/l + queries residual -> res fp16 ----
    l_lo += __shfl_xor_sync(0xffffffffu, l_lo, 1);
    l_lo += __shfl_xor_sync(0xffffffffu, l_lo, 2);
    l_hi += __shfl_xor_sync(0xffffffffu, l_hi, 1);
    l_hi += __shfl_xor_sync(0xffffffffu, l_hi, 2);
    const float inv_lo = 1.0f / l_lo, inv_hi = 1.0f / l_hi;

#pragma unroll
    for (int nf = 0; nf < 8; nf++) {
#pragma unroll
        for (int half = 0; half < 2; half++) {
            int row = q0 + wid * 16 + g + half * 8;
            int col = h * DHH + nf * 8 + t4 * 2;
            long idx = (long)(b * TT + row) * DD + col;
            float inv = half ? inv_hi : inv_lo;
            float2 r2 = *(const float2*)&queries[idx];
            float v0 = o[nf][half * 2 + 0] * inv + r2.x;
            float v1 = o[nf][half * 2 + 1] * inv + r2.y;
            *(uint32_t*)&res_[idx] = pack_h2(v0, v1);
        }
    }
}

// ---------------------------------------------------------------------------
__global__ void cvt_k(const float* __restrict__ in, h16* __restrict__ o, int n)
{
    int i = blockIdx.x * blockDim.x + threadIdx.x;
    if (i < n) o[i] = __float2half(in[i]);
}

// f32 [R,C] -> fp16 transposed [C,R]
__global__ void trcvt_k(const float* __restrict__ in, h16* __restrict__ o,
                        int R, int C)
{
    __shared__ float tile[32][33];
    int r0 = blockIdx.y * 32, c0 = blockIdx.x * 32;
    for (int i = threadIdx.y; i < 32; i += 8)
        tile[i][threadIdx.x] = in[(long)(r0 + i) * C + c0 + threadIdx.x];
    __syncthreads();
    for (int i = threadIdx.y; i < 32; i += 8)
        o[(long)(c0 + i) * R + r0 + threadIdx.x] = __float2half(tile[threadIdx.x][i]);
}

__global__ void zero_k(float* __restrict__ p, int n)
{
    int i = blockIdx.x * blockDim.x + threadIdx.x;
    if (i < n) p[i] = 0.f;
}

// out[b,d] = mean_t(res) + (S1[b,:]/T) @ fw2[:,d]
__global__ __launch_bounds__(512)
void final_k(const h16* __restrict__ rh, const float* __restrict__ S1,
             const float* __restrict__ fw2, float* __restrict__ out)
{
    __shared__ float s1s[FF];
    const int b = blockIdx.x;
    const int d = threadIdx.x;
    for (int i = threadIdx.x; i < FF; i += 512)
        s1s[i] = S1[b * FF + i] * (1.0f / (float)TT);
    __syncthreads();

    float acc = 0.f;
    const long boff = (long)b * TT * DD + d;
#pragma unroll 4
    for (int t = 0; t < TT; t++)
        acc += __half2float(rh[boff + (long)t * DD]);
    acc *= 1.0f / (float)TT;

#pragma unroll 4
    for (int f = 0; f < FF; f++) acc += s1s[f] * fw2[(long)f * DD + d];

    out[b * DD + d] = acc;
}

// ---------------------------------------------------------------------------
// Launch
// ---------------------------------------------------------------------------
extern "C" void kernel_launch(void* const* d_in, const int* in_sizes, int n_in,
                              void* d_out, int out_size)
{
    const float* queries = (const float*)d_in[0];
    const float* keys    = (const float*)d_in[1];
    const float* Wq      = (const float*)d_in[2];
    const float* Wk      = (const float*)d_in[3];
    const float* Wv      = (const float*)d_in[4];
    const float* fw1     = (const float*)d_in[5];
    const float* fw2     = (const float*)d_in[6];
    float* out = (float*)d_out;

    h16 *aq, *ak, *wqt, *wkt, *wvt, *f1t, *q, *k, *v, *res;
    float *S1;
    cudaGetSymbolAddress((void**)&aq,  g_aq);
    cudaGetSymbolAddress((void**)&ak,  g_ak);
    cudaGetSymbolAddress((void**)&wqt, g_wqt);
    cudaGetSymbolAddress((void**)&wkt, g_wkt);
    cudaGetSymbolAddress((void**)&wvt, g_wvt);
    cudaGetSymbolAddress((void**)&f1t, g_f1t);
    cudaGetSymbolAddress((void**)&q,   g_q);
    cudaGetSymbolAddress((void**)&k,   g_k);
    cudaGetSymbolAddress((void**)&v,   g_v);
    cudaGetSymbolAddress((void**)&res, g_res);
    cudaGetSymbolAddress((void**)&S1,  g_S1);

    const int SMEMG  = 3 * (128 + 128) * 72 * 2;   // 110592
    const int SMEMFA = 5 * 128 * 72 * 2;           // 92160
    cudaFuncSetAttribute(gemm_mma<128, 0>, cudaFuncAttributeMaxDynamicSharedMemorySize, SMEMG);
    cudaFuncSetAttribute(gemm_mma<128, 2>, cudaFuncAttributeMaxDynamicSharedMemorySize, SMEMG);
    cudaFuncSetAttribute(flash_attn_k, cudaFuncAttributeMaxDynamicSharedMemorySize, SMEMFA);

    // 1) input conversions
    cvt_k<<<(MTOT * DD + 511) / 512, 512>>>(queries, aq, MTOT * DD);
    cvt_k<<<(MTOT * DD + 511) / 512, 512>>>(keys,    ak, MTOT * DD);
    trcvt_k<<<dim3(DD / 32, DD / 32), dim3(32, 8)>>>(Wq,  wqt, DD, DD);
    trcvt_k<<<dim3(DD / 32, DD / 32), dim3(32, 8)>>>(Wk,  wkt, DD, DD);
    trcvt_k<<<dim3(DD / 32, DD / 32), dim3(32, 8)>>>(Wv,  wvt, DD, DD);
    trcvt_k<<<dim3(FF / 32, DD / 32), dim3(32, 8)>>>(fw1, f1t, DD, FF);

    // 2) projections: q = queries@Wq, k = keys@Wk, v = k@Wv
    gemm_mma<128, 0><<<dim3(DD / 128, MTOT / 128, 1), 256, SMEMG>>>(
        aq, DD, 0, 0,  wqt, DD, 0, 0,  1.0f, DD, 1,  q, DD, 0, 0, nullptr, nullptr);
    gemm_mma<128, 0><<<dim3(DD / 128, MTOT / 128, 1), 256, SMEMG>>>(
        ak, DD, 0, 0,  wkt, DD, 0, 0,  1.0f, DD, 1,  k, DD, 0, 0, nullptr, nullptr);
    gemm_mma<128, 0><<<dim3(DD / 128, MTOT / 128, 1), 256, SMEMG>>>(
        k, DD, 0, 0,   wvt, DD, 0, 0,  1.0f, DD, 1,  v, DD, 0, 0, nullptr, nullptr);

    // 3) fused flash attention + residual -> res
    flash_attn_k<<<dim3(TT / 128, BB * HH), 256, SMEMFA>>>(
        q, k, v, queries, res);

    // 4) FFN1: relu + per-batch column sums into S1 (FFN2 folded into final)
    zero_k<<<(BB * FF + 1023) / 1024, 1024>>>(S1, BB * FF);
    gemm_mma<128, 2><<<dim3(FF / 128, MTOT / 128, 1), 256, SMEMG>>>(
        res, DD, 0, 0,  f1t, DD, 0, 0,  1.0f, DD, 1,
        nullptr, 0, 0, 0, nullptr, S1);

    // 5) out = mean_t(res) + (S1/T) @ fw2
    final_k<<<BB, 512>>>(res, S1, fw2, out);
}

// round 8
// speedup vs baseline: 5.1478x; 1.4824x over previous
#include <cuda_runtime.h>
#include <cuda_fp16.h>
#include <cstdint>

// ---------------------------------------------------------------------------
// Problem constants
// ---------------------------------------------------------------------------
#define BB   16
#define TT   1024
#define DD   512
#define HH   8
#define DHH  64
#define MTOT (BB*TT)        // 16384
#define FF   (4*DD)         // 2048

typedef __half h16;

// ---------------------------------------------------------------------------
// Device scratch (__device__ globals; allocation-free rule)
// ---------------------------------------------------------------------------
__device__ h16   g_in [2*MTOT*DD];   // fp16 queries | keys
__device__ h16   g_w  [3*DD*DD];     // Wq^T | Wk^T | Wkv^T (n-major)
__device__ h16   g_f1t[FF*DD];       // fw1^T [2048,512]
__device__ h16   g_qkv[3*MTOT*DD];   // q | k | v
__device__ h16   g_res[MTOT*DD];
__device__ float g_S1 [BB*FF];
__device__ float g_part[BB*8*DD];

// ---------------------------------------------------------------------------
// PTX helpers (all base-PTX, sm_80-era: safe under compute_100 target)
// ---------------------------------------------------------------------------
__device__ __forceinline__ uint32_t smem_u32(const void* p) {
    return (uint32_t)__cvta_generic_to_shared((void*)p);
}
__device__ __forceinline__ void cp16(uint32_t dst, const void* src) {
    asm volatile("cp.async.cg.shared.global [%0], [%1], 16;" :: "r"(dst), "l"(src));
}
#define CP_COMMIT() asm volatile("cp.async.commit_group;" ::: "memory")
#define CP_WAIT2()  asm volatile("cp.async.wait_group 2;"  ::: "memory")
#define CP_WAIT0()  asm volatile("cp.async.wait_group 0;"  ::: "memory")

__device__ __forceinline__ void ldm_x4(uint32_t* r, uint32_t addr) {
    asm volatile("ldmatrix.sync.aligned.m8n8.x4.shared.b16 {%0,%1,%2,%3}, [%4];"
        : "=r"(r[0]), "=r"(r[1]), "=r"(r[2]), "=r"(r[3]) : "r"(addr));
}
__device__ __forceinline__ void ldm_x2(uint32_t* r, uint32_t addr) {
    asm volatile("ldmatrix.sync.aligned.m8n8.x2.shared.b16 {%0,%1}, [%2];"
        : "=r"(r[0]), "=r"(r[1]) : "r"(addr));
}
__device__ __forceinline__ void ldm_x2_trans(uint32_t* r, uint32_t addr) {
    asm volatile("ldmatrix.sync.aligned.m8n8.x2.trans.shared.b16 {%0,%1}, [%2];"
        : "=r"(r[0]), "=r"(r[1]) : "r"(addr));
}
__device__ __forceinline__ void mma16816(float* c, const uint32_t* a, const uint32_t* b) {
    asm volatile(
        "mma.sync.aligned.m16n8k16.row.col.f32.f16.f16.f32 "
        "{%0,%1,%2,%3}, {%4,%5,%6,%7}, {%8,%9}, {%0,%1,%2,%3};"
        : "+f"(c[0]), "+f"(c[1]), "+f"(c[2]), "+f"(c[3])
        : "r"(a[0]), "r"(a[1]), "r"(a[2]), "r"(a[3]), "r"(b[0]), "r"(b[1]));
}
__device__ __forceinline__ uint32_t pack_h2(float x, float y) {
    __half2 t = __floats2half2_rn(x, y);
    return *(uint32_t*)&t;
}
__device__ __forceinline__ float ex2(float x) {
    float y;
    asm("ex2.approx.f32 %0, %1;" : "=f"(y) : "f"(x));
    return y;
}

// ---------------------------------------------------------------------------
// fp16 mma.sync GEMM (single pass).  D[m][n] = sum_k A[m][k]*B[n][k].
// A [M,K] row-major, B [N,K] n-major. CTA tile 128 x BN, BK=64, 8 warps (2x4),
// 3-stage cp.async pipeline, 2 CTAs/SM.
// MAPA: projection mode — A base = A_ + ((z+1)>>1)*sAo (z0:queries, z1/2:keys),
//       B base = B_ + z*sBo, C base = C_ + z*sCo.
// EPI 0: C = alpha*D (+R residual f32) -> fp16
// EPI 2: relu(D) column sums atomically into S1[b*FF + n]
// ---------------------------------------------------------------------------
template<int BN, int EPI, bool MAPA>
__global__ __launch_bounds__(256, 2)
void gemm_mma(const h16* __restrict__ A_, int ldA, long sAo, long sAi,
              const h16* __restrict__ B_, int ldB, long sBo, long sBi,
              float alpha, int K, int ZI,
              h16* __restrict__ C_, int ldc, long sCo, long sCi,
              const float* __restrict__ Rres,
              float* __restrict__ S1)
{
    constexpr int BM = 128, LDS = 72;              // 144B pitch, conflict-free
    constexpr int NT = BN / 4;
    constexpr int NF = NT / 8;
    constexpr int MF = 4;
    constexpr int STAGE = (BM + BN) * LDS;

    extern __shared__ h16 sm[];
    const int tid = threadIdx.x, lane = tid & 31, wid = tid >> 5;
    const int wm = wid >> 2, wn = wid & 3;
    const int g = lane >> 2, t4 = lane & 3;

    const int z = blockIdx.z, zo = z / ZI, zi = z % ZI;
    const int m0 = blockIdx.y * BM, n0 = blockIdx.x * BN;

    const long aoff = MAPA ? (long)((z + 1) >> 1) * sAo
                           : (long)zo * sAo + (long)zi * sAi;
    const long boff = MAPA ? (long)z * sBo
                           : (long)zo * sBo + (long)zi * sBi;
    const long coff = MAPA ? (long)z * sCo
                           : (long)zo * sCo + (long)zi * sCi;

    const h16* Ab = A_ + aoff + (long)m0 * ldA;
    const h16* Bb = B_ + boff + (long)n0 * ldB;

    const int NC = K / 64;

    auto load_chunk = [&](int c) {
        if (c < NC) {
            h16* st = sm + (c % 3) * STAGE;
            const long koff = (long)c * 64;
            for (int i = tid; i < BM * 8; i += 256) {
                int r = i >> 3, hh = i & 7;
                cp16(smem_u32(st + r * LDS + hh * 8), Ab + (long)r * ldA + koff + hh * 8);
            }
            for (int i = tid; i < BN * 8; i += 256) {
                int r = i >> 3, hh = i & 7;
                cp16(smem_u32(st + BM * LDS + r * LDS + hh * 8),
                     Bb + (long)r * ldB + koff + hh * 8);
            }
        }
        CP_COMMIT();
    };

    float acc[MF][NF][4];
#pragma unroll
    for (int i = 0; i < MF; i++)
#pragma unroll
        for (int j = 0; j < NF; j++)
#pragma unroll
            for (int e = 0; e < 4; e++) acc[i][j][e] = 0.f;

    load_chunk(0);
    load_chunk(1);

    const int ar = lane & 15;
    const int ac8 = (lane >> 4) << 3;
    const int br = lane & 7;
    const int bc8 = ((lane >> 3) & 1) << 3;

    for (int c = 0; c < NC; c++) {
        load_chunk(c + 2);
        CP_WAIT2();
        __syncthreads();

        h16* st = sm + (c % 3) * STAGE;
        const uint32_t aS = smem_u32(st);
        const uint32_t bS = smem_u32(st + BM * LDS);

#pragma unroll
        for (int ks = 0; ks < 4; ks++) {
            uint32_t ah[MF][4], bh[NF][2];
            const int acol = ks * 16 + ac8;
#pragma unroll
            for (int mf = 0; mf < MF; mf++)
                ldm_x4(ah[mf], aS + ((wm * 64 + mf * 16 + ar) * LDS + acol) * 2);
            const int bcol = ks * 16 + bc8;
#pragma unroll
            for (int nf = 0; nf < NF; nf++)
                ldm_x2(bh[nf], bS + ((wn * NT + nf * 8 + br) * LDS + bcol) * 2);
#pragma unroll
            for (int mf = 0; mf < MF; mf++)
#pragma unroll
                for (int nf = 0; nf < NF; nf++)
                    mma16816(acc[mf][nf], ah[mf], bh[nf]);
        }
        __syncthreads();
    }

    if constexpr (EPI == 2) {
        float* cs = (float*)sm;
        if (tid < BN) cs[tid] = 0.f;
        __syncthreads();
#pragma unroll
        for (int nf = 0; nf < NF; nf++) {
            float s0 = 0.f, s1 = 0.f;
#pragma unroll
            for (int mf = 0; mf < MF; mf++) {
                s0 += fmaxf(acc[mf][nf][0], 0.f) + fmaxf(acc[mf][nf][2], 0.f);
                s1 += fmaxf(acc[mf][nf][1], 0.f) + fmaxf(acc[mf][nf][3], 0.f);
            }
            int col = wn * NT + nf * 8 + t4 * 2;
            atomicAdd(&cs[col], s0);
            atomicAdd(&cs[col + 1], s1);
        }
        __syncthreads();
        if (tid < BN)
            atomicAdd(&S1[(m0 / TT) * FF + n0 + tid], cs[tid]);
    } else {
        h16* Cb = C_ + coff;
        const float* Rb = Rres ? Rres + coff : nullptr;
#pragma unroll
        for (int mf = 0; mf < MF; mf++)
#pragma unroll
            for (int nf = 0; nf < NF; nf++) {
#pragma unroll
                for (int half = 0; half < 2; half++) {
                    long o0 = (long)(m0 + wm * 64 + mf * 16 + g + half * 8) * ldc
                            + n0 + wn * NT + nf * 8 + t4 * 2;
                    float v0 = alpha * acc[mf][nf][half * 2 + 0];
                    float v1 = alpha * acc[mf][nf][half * 2 + 1];
                    if (Rb) {
                        float2 r2 = *(const float2*)&Rb[o0];
                        v0 += r2.x; v1 += r2.y;
                    }
                    *(uint32_t*)&Cb[o0] = pack_h2(v0, v1);
                }
            }
    }
}

// ---------------------------------------------------------------------------
// Fused flash attention, fp16 single-pass. Grid (8 q-tiles, 128 b*h).
// 256 thr (8 warps x 16 rows), Q tile 128x64. V consumed from [t,d] layout
// via ldmatrix.trans. Online softmax in log2 domain + diag blinding.
// Output res = O + queries (fp16).
// ---------------------------------------------------------------------------
#define QP 72           // pitch (halfs) for 64-col tiles; 144B rows
#define SCL 0.18033688011112042f   // 0.125 * log2(e)

__global__ __launch_bounds__(256, 1)
void flash_attn_k(const h16* __restrict__ q_, const h16* __restrict__ k_,
                  const h16* __restrict__ v_,
                  const float* __restrict__ queries,
                  h16* __restrict__ res_)
{
    extern __shared__ h16 sm[];
    const int tid = threadIdx.x, lane = tid & 31, wid = tid >> 5;
    const int g = lane >> 2, t4 = lane & 3, br = lane & 7;
    const int qt = blockIdx.x, bh = blockIdx.y;
    const int b = bh >> 3, h = bh & 7;
    const int q0 = qt * 128;

    const int TILE = 128 * QP;                 // 9216
    const int QH = 0, KB = TILE, VB = 3 * TILE;

    auto stageKV = [&](int kt) {
        const int kb = KB + (kt & 1) * TILE;
        const int vb = VB + (kt & 1) * TILE;
        for (int i = tid; i < 2048; i += 256) {
            int sel = i >> 10, j = i & 1023, r = j >> 3, c = j & 7;
            const h16* src = (sel ? v_ : k_)
                + ((long)(b * TT + kt * 128 + r)) * DD + h * DHH + c * 8;
            cp16(smem_u32(sm + (sel ? vb : kb) + r * QP + c * 8), src);
        }
    };

    for (int i = tid; i < 1024; i += 256) {
        int r = i >> 3, c = i & 7;
        cp16(smem_u32(sm + QH + r * QP + c * 8),
             q_ + ((long)(b * TT + q0 + r)) * DD + h * DHH + c * 8);
    }
    stageKV(0);
    CP_COMMIT();
    CP_WAIT0();
    __syncthreads();

    uint32_t qf[4][4];
    {
        const int ar = lane & 15;
#pragma unroll
        for (int ks = 0; ks < 4; ks++) {
            int acol = ks * 16 + ((lane >> 4) << 3);
            ldm_x4(qf[ks], smem_u32(sm + QH) + ((wid * 16 + ar) * QP + acol) * 2);
        }
    }

    float o[8][4];
#pragma unroll
    for (int i = 0; i < 8; i++)
#pragma unroll
        for (int e = 0; e < 4; e++) o[i][e] = 0.f;
    float m_lo = -1e30f, m_hi = -1e30f, l_lo = 0.f, l_hi = 0.f;

    const int bc8 = ((lane >> 3) & 1) << 3;
    const int vrow = ((lane >> 3) & 1) * 8 + (lane & 7);

    for (int kt = 0; kt < 8; kt++) {
        if (kt > 0) { CP_WAIT0(); }
        __syncthreads();
        if (kt + 1 < 8) { stageKV(kt + 1); CP_COMMIT(); }

        const uint32_t kS = smem_u32(sm + KB + (kt & 1) * TILE);
        const uint32_t vS = smem_u32(sm + VB + (kt & 1) * TILE);

        // ---- S = Q K^T, 16 n-frags of 8 cols ----
        float s[16][4];
#pragma unroll
        for (int nf = 0; nf < 16; nf++) {
#pragma unroll
            for (int e = 0; e < 4; e++) s[nf][e] = 0.f;
#pragma unroll
            for (int ks = 0; ks < 4; ks++) {
                uint32_t bh2[2];
                ldm_x2(bh2, kS + ((nf * 8 + br) * QP + ks * 16 + bc8) * 2);
                mma16816(s[nf], qf[ks], bh2);
            }
        }

        // scale into log2 domain + diagonal blinding
#pragma unroll
        for (int nf = 0; nf < 16; nf++)
#pragma unroll
            for (int e = 0; e < 4; e++) s[nf][e] *= SCL;
        if (kt == qt) {
#pragma unroll
            for (int nf = 0; nf < 16; nf++)
#pragma unroll
                for (int e = 0; e < 4; e++) {
                    int row = wid * 16 + g + ((e >> 1) << 3);
                    int col = nf * 8 + t4 * 2 + (e & 1);
                    if (row == col) s[nf][e] = -1e30f;
                }
        }

        // ---- online softmax update (base-2) ----
        float mn_lo = -1e30f, mn_hi = -1e30f;
#pragma unroll
        for (int nf = 0; nf < 16; nf++) {
            mn_lo = fmaxf(mn_lo, fmaxf(s[nf][0], s[nf][1]));
            mn_hi = fmaxf(mn_hi, fmaxf(s[nf][2], s[nf][3]));
        }
        mn_lo = fmaxf(mn_lo, __shfl_xor_sync(0xffffffffu, mn_lo, 1));
        mn_lo = fmaxf(mn_lo, __shfl_xor_sync(0xffffffffu, mn_lo, 2));
        mn_hi = fmaxf(mn_hi, __shfl_xor_sync(0xffffffffu, mn_hi, 1));
        mn_hi = fmaxf(mn_hi, __shfl_xor_sync(0xffffffffu, mn_hi, 2));

        float mc_lo = fmaxf(m_lo, mn_lo), mc_hi = fmaxf(m_hi, mn_hi);
        float sc_lo = ex2(m_lo - mc_lo), sc_hi = ex2(m_hi - mc_hi);
        l_lo *= sc_lo; l_hi *= sc_hi;
#pragma unroll
        for (int nf = 0; nf < 8; nf++) {
            o[nf][0] *= sc_lo; o[nf][1] *= sc_lo;
            o[nf][2] *= sc_hi; o[nf][3] *= sc_hi;
        }
#pragma unroll
        for (int nf = 0; nf < 16; nf++) {
            s[nf][0] = ex2(s[nf][0] - mc_lo);
            s[nf][1] = ex2(s[nf][1] - mc_lo);
            s[nf][2] = ex2(s[nf][2] - mc_hi);
            s[nf][3] = ex2(s[nf][3] - mc_hi);
            l_lo += s[nf][0] + s[nf][1];
            l_hi += s[nf][2] + s[nf][3];
        }
        m_lo = mc_lo; m_hi = mc_hi;

        // ---- O += P V ; S-acc layout == A-frag layout; V via ldmatrix.trans ----
#pragma unroll
        for (int ks = 0; ks < 8; ks++) {
            uint32_t pa[4];
            pa[0] = pack_h2(s[2*ks][0],   s[2*ks][1]);
            pa[1] = pack_h2(s[2*ks][2],   s[2*ks][3]);
            pa[2] = pack_h2(s[2*ks+1][0], s[2*ks+1][1]);
            pa[3] = pack_h2(s[2*ks+1][2], s[2*ks+1][3]);
#pragma unroll
            for (int nf = 0; nf < 8; nf++) {
                uint32_t vb2[2];
                ldm_x2_trans(vb2, vS + ((ks * 16 + vrow) * QP + nf * 8) * 2);
                mma16816(o[nf], pa, vb2);
            }
        }
        __syncthreads();
    }

    // ---- epilogue: O/l + queries residual -> res fp16 ----
    l_lo += __shfl_xor_sync(0xffffffffu, l_lo, 1);
    l_lo += __shfl_xor_sync(0xffffffffu, l_lo, 2);
    l_hi += __shfl_xor_sync(0xffffffffu, l_hi, 1);
    l_hi += __shfl_xor_sync(0xffffffffu, l_hi, 2);
    const float inv_lo = 1.0f / l_lo, inv_hi = 1.0f / l_hi;

#pragma unroll
    for (int nf = 0; nf < 8; nf++) {
#pragma unroll
        for (int half = 0; half < 2; half++) {
            int row = q0 + wid * 16 + g + half * 8;
            int col = h * DHH + nf * 8 + t4 * 2;
            long idx = (long)(b * TT + row) * DD + col;
            float inv = half ? inv_hi : inv_lo;
            float2 r2 = *(const float2*)&queries[idx];
            float v0 = o[nf][half * 2 + 0] * inv + r2.x;
            float v1 = o[nf][half * 2 + 1] * inv + r2.y;
            *(uint32_t*)&res_[idx] = pack_h2(v0, v1);
        }
    }
}

// ---------------------------------------------------------------------------
// Vectorized f32 -> fp16 (4 at a time)
__global__ void cvt4_k(const float4* __restrict__ in, uint2* __restrict__ o, int n4)
{
    int i = blockIdx.x * blockDim.x + threadIdx.x;
    if (i < n4) {
        float4 v = in[i];
        uint2 r;
        r.x = pack_h2(v.x, v.y);
        r.y = pack_h2(v.z, v.w);
        o[i] = r;
    }
}

// f32 [R,C] -> fp16 transposed [C,R]
__global__ void trcvt_k(const float* __restrict__ in, h16* __restrict__ o,
                        int R, int C)
{
    __shared__ float tile[32][33];
    int r0 = blockIdx.y * 32, c0 = blockIdx.x * 32;
    for (int i = threadIdx.y; i < 32; i += 8)
        tile[i][threadIdx.x] = in[(long)(r0 + i) * C + c0 + threadIdx.x];
    __syncthreads();
    for (int i = threadIdx.y; i < 32; i += 8)
        o[(long)(c0 + i) * R + r0 + threadIdx.x] = __float2half(tile[threadIdx.x][i]);
}

// Wkv^T[j][i] = sum_c Wk[i][c] * Wv[c][j]   (f32 compute, fp16 out, n-major)
__global__ void wkv_k(const float* __restrict__ Wk, const float* __restrict__ Wv,
                      h16* __restrict__ o)
{
    __shared__ float a[32][33];   // Wk tile: a[i-local][c-local]
    __shared__ float bsh[32][33]; // Wv tile: b[c-local][j-local]
    const int i0 = blockIdx.x * 32, j0 = blockIdx.y * 32;
    const int tx = threadIdx.x, ty = threadIdx.y;
    float acc[4] = {0.f, 0.f, 0.f, 0.f};

    for (int c0 = 0; c0 < DD; c0 += 32) {
        for (int r = ty; r < 32; r += 8) {
            a[r][tx]   = Wk[(long)(i0 + r) * DD + c0 + tx];
            bsh[r][tx] = Wv[(long)(c0 + r) * DD + j0 + tx];
        }
        __syncthreads();
#pragma unroll
        for (int cc = 0; cc < 32; cc++)
#pragma unroll
            for (int r = 0; r < 4; r++)
                acc[r] += a[ty + 8 * r][cc] * bsh[cc][tx];
        __syncthreads();
    }
#pragma unroll
    for (int r = 0; r < 4; r++)
        o[(long)(j0 + tx) * DD + i0 + ty + 8 * r] = __float2half(acc[r]);
}

__global__ void zero_k(float* __restrict__ p, int n)
{
    int i = blockIdx.x * blockDim.x + threadIdx.x;
    if (i < n) p[i] = 0.f;
}

// partial[b][j][d] = (1/T) sum_{t in j-th 128} res[b,t,d]
//                  + sum_{f in j-th 256} (S1[b,f]/T) * fw2[f,d]
__global__ __launch_bounds__(512)
void final2_k(const h16* __restrict__ rh, const float* __restrict__ S1,
              const float* __restrict__ fw2, float* __restrict__ part)
{
    __shared__ float s1s[256];
    const int j = blockIdx.x, b = blockIdx.y;
    const int d = threadIdx.x;
    if (threadIdx.x < 256)
        s1s[threadIdx.x] = S1[b * FF + j * 256 + threadIdx.x] * (1.0f / (float)TT);
    __syncthreads();

    float acc = 0.f;
    const long boff = (long)(b * TT + j * 128) * DD + d;
#pragma unroll 4
    for (int t = 0; t < 128; t++)
        acc += __half2float(rh[boff + (long)t * DD]);
    acc *= 1.0f / (float)TT;

    const float* f2 = fw2 + (long)(j * 256) * DD + d;
#pragma unroll 4
    for (int f = 0; f < 256; f++) acc += s1s[f] * f2[(long)f * DD];

    part[(long)(b * 8 + j) * DD + d] = acc;
}

// out[b,d] = sum_j part[b][j][d]
__global__ __launch_bounds__(512)
void final3_k(const float* __restrict__ part, float* __restrict__ out)
{
    const int b = blockIdx.x, d = threadIdx.x;
    float acc = 0.f;
#pragma unroll
    for (int j = 0; j < 8; j++)
        acc += part[(long)(b * 8 + j) * DD + d];
    out[b * DD + d] = acc;
}

// ---------------------------------------------------------------------------
// Launch
// ---------------------------------------------------------------------------
extern "C" void kernel_launch(void* const* d_in, const int* in_sizes, int n_in,
                              void* d_out, int out_size)
{
    const float* queries = (const float*)d_in[0];
    const float* keys    = (const float*)d_in[1];
    const float* Wq      = (const float*)d_in[2];
    const float* Wk      = (const float*)d_in[3];
    const float* Wv      = (const float*)d_in[4];
    const float* fw1     = (const float*)d_in[5];
    const float* fw2     = (const float*)d_in[6];
    float* out = (float*)d_out;

    h16 *gin, *gw, *gqkv, *res, *f1t;
    float *S1, *part;
    cudaGetSymbolAddress((void**)&gin,  g_in);
    cudaGetSymbolAddress((void**)&gw,   g_w);
    cudaGetSymbolAddress((void**)&f1t,  g_f1t);
    cudaGetSymbolAddress((void**)&gqkv, g_qkv);
    cudaGetSymbolAddress((void**)&res,  g_res);
    cudaGetSymbolAddress((void**)&S1,   g_S1);
    cudaGetSymbolAddress((void**)&part, g_part);

    const long MD = (long)MTOT * DD;
    const int SMEMG  = 3 * (128 + 128) * 72 * 2;   // 110592
    const int SMEMFA = 5 * 128 * 72 * 2;           // 92160
    cudaFuncSetAttribute(gemm_mma<128, 0, true>,  cudaFuncAttributeMaxDynamicSharedMemorySize, SMEMG);
    cudaFuncSetAttribute(gemm_mma<128, 2, false>, cudaFuncAttributeMaxDynamicSharedMemorySize, SMEMG);
    cudaFuncSetAttribute(flash_attn_k, cudaFuncAttributeMaxDynamicSharedMemorySize, SMEMFA);

    // 1) conversions + weight prep (all independent)
    cvt4_k<<<(MTOT * DD / 4 + 511) / 512, 512>>>((const float4*)queries, (uint2*)gin, MTOT * DD / 4);
    cvt4_k<<<(MTOT * DD / 4 + 511) / 512, 512>>>((const float4*)keys, (uint2*)(gin + MD), MTOT * DD / 4);
    trcvt_k<<<dim3(DD / 32, DD / 32), dim3(32, 8)>>>(Wq, gw, DD, DD);
    trcvt_k<<<dim3(DD / 32, DD / 32), dim3(32, 8)>>>(Wk, gw + DD * DD, DD, DD);
    wkv_k<<<dim3(16, 16), dim3(32, 8)>>>(Wk, Wv, gw + 2 * DD * DD);
    trcvt_k<<<dim3(FF / 32, DD / 32), dim3(32, 8)>>>(fw1, f1t, DD, FF);
    zero_k<<<(BB * FF + 1023) / 1024, 1024>>>(S1, BB * FF);

    // 2) projections q|k|v in ONE batched launch (z = 0,1,2)
    gemm_mma<128, 0, true><<<dim3(DD / 128, MTOT / 128, 3), 256, SMEMG>>>(
        gin, DD, MD, 0,  gw, DD, (long)DD * DD, 0,  1.0f, DD, 1,
        gqkv, DD, MD, 0, nullptr, nullptr);

    // 3) fused flash attention + residual -> res
    flash_attn_k<<<dim3(TT / 128, BB * HH), 256, SMEMFA>>>(
        gqkv, gqkv + MD, gqkv + 2 * MD, queries, res);

    // 4) FFN1: relu + per-batch column sums into S1
    gemm_mma<128, 2, false><<<dim3(FF / 128, MTOT / 128, 1), 256, SMEMG>>>(
        res, DD, 0, 0,  f1t, DD, 0, 0,  1.0f, DD, 1,
        nullptr, 0, 0, 0, nullptr, S1);

    // 5) out = mean_t(res) + (S1/T) @ fw2   (parallel partials + reduce)
    final2_k<<<dim3(8, BB), 512>>>(res, S1, fw2, part);
    final3_k<<<BB, 512>>>(part, out);
}

// round 9
// speedup vs baseline: 5.2076x; 1.0116x over previous
#include <cuda_runtime.h>
#include <cuda_fp16.h>
#include <cstdint>

// ---------------------------------------------------------------------------
// Problem constants
// ---------------------------------------------------------------------------
#define BB   16
#define TT   1024
#define DD   512
#define HH   8
#define DHH  64
#define MTOT (BB*TT)        // 16384
#define FF   (4*DD)         // 2048

typedef __half h16;

// ---------------------------------------------------------------------------
// Device scratch (__device__ globals; allocation-free rule)
// ---------------------------------------------------------------------------
__device__ h16   g_in [2*MTOT*DD];   // fp16 queries | keys
__device__ h16   g_w  [3*DD*DD];     // Wq^T | Wk^T | Wkv^T (n-major)
__device__ h16   g_f1t[FF*DD];       // fw1^T [2048,512]
__device__ h16   g_qkv[3*MTOT*DD];   // q | k | v
__device__ h16   g_res[MTOT*DD];
__device__ float g_S1 [BB*FF];
__device__ float g_part[BB*8*DD];

// ---------------------------------------------------------------------------
// PTX helpers (all base-PTX, sm_80-era: safe under compute_100 target)
// ---------------------------------------------------------------------------
__device__ __forceinline__ uint32_t smem_u32(const void* p) {
    return (uint32_t)__cvta_generic_to_shared((void*)p);
}
__device__ __forceinline__ void cp16(uint32_t dst, const void* src) {
    asm volatile("cp.async.cg.shared.global [%0], [%1], 16;" :: "r"(dst), "l"(src));
}
#define CP_COMMIT() asm volatile("cp.async.commit_group;" ::: "memory")
#define CP_WAIT2()  asm volatile("cp.async.wait_group 2;"  ::: "memory")
#define CP_WAIT0()  asm volatile("cp.async.wait_group 0;"  ::: "memory")

__device__ __forceinline__ void ldm_x4(uint32_t* r, uint32_t addr) {
    asm volatile("ldmatrix.sync.aligned.m8n8.x4.shared.b16 {%0,%1,%2,%3}, [%4];"
        : "=r"(r[0]), "=r"(r[1]), "=r"(r[2]), "=r"(r[3]) : "r"(addr));
}
__device__ __forceinline__ void ldm_x4_trans(uint32_t* r, uint32_t addr) {
    asm volatile("ldmatrix.sync.aligned.m8n8.x4.trans.shared.b16 {%0,%1,%2,%3}, [%4];"
        : "=r"(r[0]), "=r"(r[1]), "=r"(r[2]), "=r"(r[3]) : "r"(addr));
}
__device__ __forceinline__ void mma16816(float* c, const uint32_t* a, const uint32_t* b) {
    asm volatile(
        "mma.sync.aligned.m16n8k16.row.col.f32.f16.f16.f32 "
        "{%0,%1,%2,%3}, {%4,%5,%6,%7}, {%8,%9}, {%0,%1,%2,%3};"
        : "+f"(c[0]), "+f"(c[1]), "+f"(c[2]), "+f"(c[3])
        : "r"(a[0]), "r"(a[1]), "r"(a[2]), "r"(a[3]), "r"(b[0]), "r"(b[1]));
}
__device__ __forceinline__ uint32_t pack_h2(float x, float y) {
    __half2 t = __floats2half2_rn(x, y);
    return *(uint32_t*)&t;
}
__device__ __forceinline__ float ex2(float x) {
    float y;
    asm("ex2.approx.f32 %0, %1;" : "=f"(y) : "f"(x));
    return y;
}

// ---------------------------------------------------------------------------
// fp16 mma.sync GEMM (single pass).  D[m][n] = sum_k A[m][k]*B[n][k].
// A [M,K] row-major, B [N,K] n-major. CTA tile 128 x BN, BK=64, 8 warps (2x4),
// 3-stage cp.async pipeline, 2 CTAs/SM. B-frags via ldmatrix.x4 (2 frags/instr).
// MAPA: projection mode — A base = A_ + ((z+1)>>1)*sAo (z0:queries, z1/2:keys),
//       B base = B_ + z*sBo, C base = C_ + z*sCo.
// EPI 0: C = alpha*D -> fp16      EPI 2: relu(D) col sums -> S1[b*FF + n]
// ---------------------------------------------------------------------------
template<int BN, int EPI, bool MAPA>
__global__ __launch_bounds__(256, 2)
void gemm_mma(const h16* __restrict__ A_, int ldA, long sAo, long sAi,
              const h16* __restrict__ B_, int ldB, long sBo, long sBi,
              float alpha, int K, int ZI,
              h16* __restrict__ C_, int ldc, long sCo, long sCi,
              float* __restrict__ S1)
{
    constexpr int BM = 128, LDS = 72;              // 144B pitch, conflict-free
    constexpr int NT = BN / 4;
    constexpr int NF = NT / 8;                     // 4 (even)
    constexpr int MF = 4;
    constexpr int STAGE = (BM + BN) * LDS;

    extern __shared__ h16 sm[];
    const int tid = threadIdx.x, lane = tid & 31, wid = tid >> 5;
    const int wm = wid >> 2, wn = wid & 3;
    const int g = lane >> 2, t4 = lane & 3;

    const int z = blockIdx.z, zo = z / ZI, zi = z % ZI;
    const int m0 = blockIdx.y * BM, n0 = blockIdx.x * BN;

    const long aoff = MAPA ? (long)((z + 1) >> 1) * sAo
                           : (long)zo * sAo + (long)zi * sAi;
    const long boff = MAPA ? (long)z * sBo
                           : (long)zo * sBo + (long)zi * sBi;
    const long coff = MAPA ? (long)z * sCo
                           : (long)zo * sCo + (long)zi * sCi;

    const h16* Ab = A_ + aoff + (long)m0 * ldA;
    const h16* Bb = B_ + boff + (long)n0 * ldB;

    const int NC = K / 64;

    auto load_chunk = [&](int c) {
        if (c < NC) {
            h16* st = sm + (c % 3) * STAGE;
            const long koff = (long)c * 64;
            for (int i = tid; i < BM * 8; i += 256) {
                int r = i >> 3, hh = i & 7;
                cp16(smem_u32(st + r * LDS + hh * 8), Ab + (long)r * ldA + koff + hh * 8);
            }
            for (int i = tid; i < BN * 8; i += 256) {
                int r = i >> 3, hh = i & 7;
                cp16(smem_u32(st + BM * LDS + r * LDS + hh * 8),
                     Bb + (long)r * ldB + koff + hh * 8);
            }
        }
        CP_COMMIT();
    };

    float acc[MF][NF][4];
#pragma unroll
    for (int i = 0; i < MF; i++)
#pragma unroll
        for (int j = 0; j < NF; j++)
#pragma unroll
            for (int e = 0; e < 4; e++) acc[i][j][e] = 0.f;

    load_chunk(0);
    load_chunk(1);

    const int ar  = lane & 15;
    const int ac8 = (lane >> 4) << 3;
    const int br  = lane & 7;
    const int selk = (lane >> 3) & 1;          // which k-half (x4 B load)
    const int sel2 = (lane >> 4) & 1;          // which n-frag of the pair

    for (int c = 0; c < NC; c++) {
        load_chunk(c + 2);
        CP_WAIT2();
        __syncthreads();

        h16* st = sm + (c % 3) * STAGE;
        const uint32_t aS = smem_u32(st);
        const uint32_t bS = smem_u32(st + BM * LDS);

#pragma unroll
        for (int ks = 0; ks < 4; ks++) {
            uint32_t ah[MF][4], bh[NF][2];
            const int acol = ks * 16 + ac8;
#pragma unroll
            for (int mf = 0; mf < MF; mf++)
                ldm_x4(ah[mf], aS + ((wm * 64 + mf * 16 + ar) * LDS + acol) * 2);
#pragma unroll
            for (int nf2 = 0; nf2 < NF / 2; nf2++) {
                uint32_t bb[4];
                int row = wn * NT + (nf2 * 2 + sel2) * 8 + br;
                int col = ks * 16 + selk * 8;
                ldm_x4(bb, bS + (row * LDS + col) * 2);
                bh[nf2 * 2 + 0][0] = bb[0]; bh[nf2 * 2 + 0][1] = bb[1];
                bh[nf2 * 2 + 1][0] = bb[2]; bh[nf2 * 2 + 1][1] = bb[3];
            }
#pragma unroll
            for (int mf = 0; mf < MF; mf++)
#pragma unroll
                for (int nf = 0; nf < NF; nf++)
                    mma16816(acc[mf][nf], ah[mf], bh[nf]);
        }
        __syncthreads();
    }

    if constexpr (EPI == 2) {
        float* cs = (float*)sm;
        if (tid < BN) cs[tid] = 0.f;
        __syncthreads();
#pragma unroll
        for (int nf = 0; nf < NF; nf++) {
            float s0 = 0.f, s1 = 0.f;
#pragma unroll
            for (int mf = 0; mf < MF; mf++) {
                s0 += fmaxf(acc[mf][nf][0], 0.f) + fmaxf(acc[mf][nf][2], 0.f);
                s1 += fmaxf(acc[mf][nf][1], 0.f) + fmaxf(acc[mf][nf][3], 0.f);
            }
            int col = wn * NT + nf * 8 + t4 * 2;
            atomicAdd(&cs[col], s0);
            atomicAdd(&cs[col + 1], s1);
        }
        __syncthreads();
        if (tid < BN)
            atomicAdd(&S1[(m0 / TT) * FF + n0 + tid], cs[tid]);
    } else {
        h16* Cb = C_ + coff;
#pragma unroll
        for (int mf = 0; mf < MF; mf++)
#pragma unroll
            for (int nf = 0; nf < NF; nf++) {
#pragma unroll
                for (int half = 0; half < 2; half++) {
                    long o0 = (long)(m0 + wm * 64 + mf * 16 + g + half * 8) * ldc
                            + n0 + wn * NT + nf * 8 + t4 * 2;
                    *(uint32_t*)&Cb[o0] = pack_h2(alpha * acc[mf][nf][half * 2 + 0],
                                                  alpha * acc[mf][nf][half * 2 + 1]);
                }
            }
    }
}

// ---------------------------------------------------------------------------
// Fused flash attention, fp16 single-pass. Grid (8 q-tiles, 128 b*h).
// 256 thr (8 warps x 16 rows), Q tile 128x64. V from [t,d] via ldmatrix.x4.trans,
// K-frags via ldmatrix.x4 (2 n-frags per instr). Online softmax (base-2) + diag
// blinding. Output res = O + queries (fp16).
// ---------------------------------------------------------------------------
#define QP 72           // pitch (halfs); 144B rows
#define SCL 0.18033688011112042f   // 0.125 * log2(e)

__global__ __launch_bounds__(256, 1)
void flash_attn_k(const h16* __restrict__ q_, const h16* __restrict__ k_,
                  const h16* __restrict__ v_,
                  const float* __restrict__ queries,
                  h16* __restrict__ res_)
{
    extern __shared__ h16 sm[];
    const int tid = threadIdx.x, lane = tid & 31, wid = tid >> 5;
    const int g = lane >> 2, t4 = lane & 3, br = lane & 7;
    const int qt = blockIdx.x, bh = blockIdx.y;
    const int b = bh >> 3, h = bh & 7;
    const int q0 = qt * 128;

    const int TILE = 128 * QP;                 // 9216
    const int QH = 0, KB = TILE, VB = 3 * TILE;

    auto stageKV = [&](int kt) {
        const int kb = KB + (kt & 1) * TILE;
        const int vb = VB + (kt & 1) * TILE;
        for (int i = tid; i < 2048; i += 256) {
            int sel = i >> 10, j = i & 1023, r = j >> 3, c = j & 7;
            const h16* src = (sel ? v_ : k_)
                + ((long)(b * TT + kt * 128 + r)) * DD + h * DHH + c * 8;
            cp16(smem_u32(sm + (sel ? vb : kb) + r * QP + c * 8), src);
        }
    };

    for (int i = tid; i < 1024; i += 256) {
        int r = i >> 3, c = i & 7;
        cp16(smem_u32(sm + QH + r * QP + c * 8),
             q_ + ((long)(b * TT + q0 + r)) * DD + h * DHH + c * 8);
    }
    stageKV(0);
    CP_COMMIT();
    CP_WAIT0();
    __syncthreads();

    uint32_t qf[4][4];
    {
        const int ar = lane & 15;
#pragma unroll
        for (int ks = 0; ks < 4; ks++) {
            int acol = ks * 16 + ((lane >> 4) << 3);
            ldm_x4(qf[ks], smem_u32(sm + QH) + ((wid * 16 + ar) * QP + acol) * 2);
        }
    }

    float o[8][4];
#pragma unroll
    for (int i = 0; i < 8; i++)
#pragma unroll
        for (int e = 0; e < 4; e++) o[i][e] = 0.f;
    float m_lo = -1e30f, m_hi = -1e30f, l_lo = 0.f, l_hi = 0.f;

    const int selk = (lane >> 3) & 1;
    const int sel2 = (lane >> 4) & 1;
    const int grp  = lane >> 3;                // 0..3 (x4.trans groups)

    for (int kt = 0; kt < 8; kt++) {
        if (kt > 0) { CP_WAIT0(); }
        __syncthreads();
        if (kt + 1 < 8) { stageKV(kt + 1); CP_COMMIT(); }

        const uint32_t kS = smem_u32(sm + KB + (kt & 1) * TILE);
        const uint32_t vS = smem_u32(sm + VB + (kt & 1) * TILE);

        // ---- S = Q K^T; K-frags 2-at-a-time via x4 ----
        float s[16][4];
#pragma unroll
        for (int nf2 = 0; nf2 < 8; nf2++) {
#pragma unroll
            for (int e = 0; e < 4; e++) {
                s[2*nf2][e] = 0.f; s[2*nf2+1][e] = 0.f;
            }
#pragma unroll
            for (int ks = 0; ks < 4; ks++) {
                uint32_t bb[4];
                int row = (nf2 * 2 + sel2) * 8 + br;
                int col = ks * 16 + selk * 8;
                ldm_x4(bb, kS + (row * QP + col) * 2);
                mma16816(s[2*nf2],   qf[ks], bb + 0);
                mma16816(s[2*nf2+1], qf[ks], bb + 2);
            }
        }

        // scale into log2 domain + diagonal blinding
#pragma unroll
        for (int nf = 0; nf < 16; nf++)
#pragma unroll
            for (int e = 0; e < 4; e++) s[nf][e] *= SCL;
        if (kt == qt) {
#pragma unroll
            for (int nf = 0; nf < 16; nf++)
#pragma unroll
                for (int e = 0; e < 4; e++) {
                    int row = wid * 16 + g + ((e >> 1) << 3);
                    int col = nf * 8 + t4 * 2 + (e & 1);
                    if (row == col) s[nf][e] = -1e30f;
                }
        }

        // ---- online softmax update (base-2) ----
        float mn_lo = -1e30f, mn_hi = -1e30f;
#pragma unroll
        for (int nf = 0; nf < 16; nf++) {
            mn_lo = fmaxf(mn_lo, fmaxf(s[nf][0], s[nf][1]));
            mn_hi = fmaxf(mn_hi, fmaxf(s[nf][2], s[nf][3]));
        }
        mn_lo = fmaxf(mn_lo, __shfl_xor_sync(0xffffffffu, mn_lo, 1));
        mn_lo = fmaxf(mn_lo, __shfl_xor_sync(0xffffffffu, mn_lo, 2));
        mn_hi = fmaxf(mn_hi, __shfl_xor_sync(0xffffffffu, mn_hi, 1));
        mn_hi = fmaxf(mn_hi, __shfl_xor_sync(0xffffffffu, mn_hi, 2));

        float mc_lo = fmaxf(m_lo, mn_lo), mc_hi = fmaxf(m_hi, mn_hi);
        float sc_lo = ex2(m_lo - mc_lo), sc_hi = ex2(m_hi - mc_hi);
        l_lo *= sc_lo; l_hi *= sc_hi;
#pragma unroll
        for (int nf = 0; nf < 8; nf++) {
            o[nf][0] *= sc_lo; o[nf][1] *= sc_lo;
            o[nf][2] *= sc_hi; o[nf][3] *= sc_hi;
        }
#pragma unroll
        for (int nf = 0; nf < 16; nf++) {
            s[nf][0] = ex2(s[nf][0] - mc_lo);
            s[nf][1] = ex2(s[nf][1] - mc_lo);
            s[nf][2] = ex2(s[nf][2] - mc_hi);
            s[nf][3] = ex2(s[nf][3] - mc_hi);
            l_lo += s[nf][0] + s[nf][1];
            l_hi += s[nf][2] + s[nf][3];
        }
        m_lo = mc_lo; m_hi = mc_hi;

        // ---- O += P V ; V-frags 2-at-a-time via x4.trans ----
#pragma unroll
        for (int ks = 0; ks < 8; ks++) {
            uint32_t pa[4];
            pa[0] = pack_h2(s[2*ks][0],   s[2*ks][1]);
            pa[1] = pack_h2(s[2*ks][2],   s[2*ks][3]);
            pa[2] = pack_h2(s[2*ks+1][0], s[2*ks+1][1]);
            pa[3] = pack_h2(s[2*ks+1][2], s[2*ks+1][3]);
#pragma unroll
            for (int nf2 = 0; nf2 < 4; nf2++) {
                uint32_t vv[4];
                int row = ks * 16 + (grp & 1) * 8 + br;
                int col = (nf2 * 2 + (grp >> 1)) * 8;
                ldm_x4_trans(vv, vS + (row * QP + col) * 2);
                mma16816(o[2*nf2],   pa, vv + 0);
                mma16816(o[2*nf2+1], pa, vv + 2);
            }
        }
        __syncthreads();
    }

    // ---- epilogue: O/l + queries residual -> res fp16 ----
    l_lo += __shfl_xor_sync(0xffffffffu, l_lo, 1);
    l_lo += __shfl_xor_sync(0xffffffffu, l_lo, 2);
    l_hi += __shfl_xor_sync(0xffffffffu, l_hi, 1);
    l_hi += __shfl_xor_sync(0xffffffffu, l_hi, 2);
    const float inv_lo = 1.0f / l_lo, inv_hi = 1.0f / l_hi;

#pragma unroll
    for (int nf = 0; nf < 8; nf++) {
#pragma unroll
        for (int half = 0; half < 2; half++) {
            int row = q0 + wid * 16 + g + half * 8;
            int col = h * DHH + nf * 8 + t4 * 2;
            long idx = (long)(b * TT + row) * DD + col;
            float inv = half ? inv_hi : inv_lo;
            float2 r2 = *(const float2*)&queries[idx];
            float v0 = o[nf][half * 2 + 0] * inv + r2.x;
            float v1 = o[nf][half * 2 + 1] * inv + r2.y;
            *(uint32_t*)&res_[idx] = pack_h2(v0, v1);
        }
    }
}

// ---------------------------------------------------------------------------
// Fused prep: all conversions + weight prep + S1 zero in ONE launch.
// Zones by blockIdx.x; uniform 256-thread blocks.
//   [0, 4096)      cvt queries -> g_in[0]
//   [4096, 8192)   cvt keys    -> g_in[MD]
//   [8192, 8448)   trcvt Wq    -> g_w[0]
//   [8448, 8704)   trcvt Wk    -> g_w[DD*DD]
//   [8704, 8960)   wkv (Wk@Wv)^T -> g_w[2*DD*DD]
//   [8960, 9984)   trcvt fw1   -> g_f1t
//   [9984, 10016)  zero S1
// ---------------------------------------------------------------------------
__device__ void dev_trcvt(const float* in, h16* o, int R, int C, int bx, int by,
                          int tx, int ty)
{
    __shared__ float tile[32][33];
    int r0 = by * 32, c0 = bx * 32;
    for (int i = ty; i < 32; i += 8)
        tile[i][tx] = in[(long)(r0 + i) * C + c0 + tx];
    __syncthreads();
    for (int i = ty; i < 32; i += 8)
        o[(long)(c0 + i) * R + r0 + tx] = __float2half(tile[tx][i]);
}

__global__ __launch_bounds__(256)
void prep_k(const float* __restrict__ queries, const float* __restrict__ keys,
            const float* __restrict__ Wq, const float* __restrict__ Wk,
            const float* __restrict__ Wv, const float* __restrict__ fw1,
            h16* __restrict__ gin, h16* __restrict__ gw,
            h16* __restrict__ f1t, float* __restrict__ S1)
{
    const int blk = blockIdx.x, tid = threadIdx.x;
    const int tx = tid & 31, ty = tid >> 5;
    const long MD = (long)MTOT * DD;

    if (blk < 8192) {                       // cvt queries / keys
        const float4* in = (const float4*)(blk < 4096 ? queries : keys);
        uint2* o = (uint2*)(blk < 4096 ? gin : gin + MD);
        int l = (blk & 4095) * 512 + tid;
#pragma unroll
        for (int rep = 0; rep < 2; rep++, l += 256) {
            float4 v = in[l];
            uint2 r;
            r.x = pack_h2(v.x, v.y);
            r.y = pack_h2(v.z, v.w);
            o[l] = r;
        }
    } else if (blk < 8448) {                // trcvt Wq
        int l = blk - 8192;
        dev_trcvt(Wq, gw, DD, DD, l & 15, l >> 4, tx, ty);
    } else if (blk < 8704) {                // trcvt Wk
        int l = blk - 8448;
        dev_trcvt(Wk, gw + DD * DD, DD, DD, l & 15, l >> 4, tx, ty);
    } else if (blk < 8960) {                // wkv
        int l = blk - 8704;
        __shared__ float a[32][33];
        __shared__ float bsh[32][33];
        const int i0 = (l & 15) * 32, j0 = (l >> 4) * 32;
        float acc[4] = {0.f, 0.f, 0.f, 0.f};
        for (int c0 = 0; c0 < DD; c0 += 32) {
            for (int r = ty; r < 32; r += 8) {
                a[r][tx]   = Wk[(long)(i0 + r) * DD + c0 + tx];
                bsh[r][tx] = Wv[(long)(c0 + r) * DD + j0 + tx];
            }
            __syncthreads();
#pragma unroll
            for (int cc = 0; cc < 32; cc++)
#pragma unroll
                for (int r = 0; r < 4; r++)
                    acc[r] += a[ty + 8 * r][cc] * bsh[cc][tx];
            __syncthreads();
        }
#pragma unroll
        for (int r = 0; r < 4; r++)
            gw[2 * DD * DD + (long)(j0 + tx) * DD + i0 + ty + 8 * r] = __float2half(acc[r]);
    } else if (blk < 9984) {                // trcvt fw1
        int l = blk - 8960;
        dev_trcvt(fw1, f1t, DD, FF, l & 63, l >> 6, tx, ty);
    } else {                                // zero S1
        int l = (blk - 9984) * 1024 + tid * 4;
        *(float4*)&S1[l] = make_float4(0.f, 0.f, 0.f, 0.f);
    }
}

// partial[b][j][d] = (1/T) sum_{t in j-th 128} res[b,t,d]
//                  + sum_{f in j-th 256} (S1[b,f]/T) * fw2[f,d]
__global__ __launch_bounds__(512)
void final2_k(const h16* __restrict__ rh, const float* __restrict__ S1,
              const float* __restrict__ fw2, float* __restrict__ part)
{
    __shared__ float s1s[256];
    const int j = blockIdx.x, b = blockIdx.y;
    const int d = threadIdx.x;
    if (threadIdx.x < 256)
        s1s[threadIdx.x] = S1[b * FF + j * 256 + threadIdx.x] * (1.0f / (float)TT);
    __syncthreads();

    float acc = 0.f;
    const long boff = (long)(b * TT + j * 128) * DD + d;
#pragma unroll 4
    for (int t = 0; t < 128; t++)
        acc += __half2float(rh[boff + (long)t * DD]);
    acc *= 1.0f / (float)TT;

    const float* f2 = fw2 + (long)(j * 256) * DD + d;
#pragma unroll 4
    for (int f = 0; f < 256; f++) acc += s1s[f] * f2[(long)f * DD];

    part[(long)(b * 8 + j) * DD + d] = acc;
}

// out[b,d] = sum_j part[b][j][d]
__global__ __launch_bounds__(512)
void final3_k(const float* __restrict__ part, float* __restrict__ out)
{
    const int b = blockIdx.x, d = threadIdx.x;
    float acc = 0.f;
#pragma unroll
    for (int j = 0; j < 8; j++)
        acc += part[(long)(b * 8 + j) * DD + d];
    out[b * DD + d] = acc;
}

// ---------------------------------------------------------------------------
// Launch
// ---------------------------------------------------------------------------
extern "C" void kernel_launch(void* const* d_in, const int* in_sizes, int n_in,
                              void* d_out, int out_size)
{
    const float* queries = (const float*)d_in[0];
    const float* keys    = (const float*)d_in[1];
    const float* Wq      = (const float*)d_in[2];
    const float* Wk      = (const float*)d_in[3];
    const float* Wv      = (const float*)d_in[4];
    const float* fw1     = (const float*)d_in[5];
    const float* fw2     = (const float*)d_in[6];
    float* out = (float*)d_out;

    h16 *gin, *gw, *gqkv, *res, *f1t;
    float *S1, *part;
    cudaGetSymbolAddress((void**)&gin,  g_in);
    cudaGetSymbolAddress((void**)&gw,   g_w);
    cudaGetSymbolAddress((void**)&f1t,  g_f1t);
    cudaGetSymbolAddress((void**)&gqkv, g_qkv);
    cudaGetSymbolAddress((void**)&res,  g_res);
    cudaGetSymbolAddress((void**)&S1,   g_S1);
    cudaGetSymbolAddress((void**)&part, g_part);

    const long MD = (long)MTOT * DD;
    const int SMEMG  = 3 * (128 + 128) * 72 * 2;   // 110592
    const int SMEMFA = 5 * 128 * 72 * 2;           // 92160
    cudaFuncSetAttribute(gemm_mma<128, 0, true>,  cudaFuncAttributeMaxDynamicSharedMemorySize, SMEMG);
    cudaFuncSetAttribute(gemm_mma<128, 2, false>, cudaFuncAttributeMaxDynamicSharedMemorySize, SMEMG);
    cudaFuncSetAttribute(flash_attn_k, cudaFuncAttributeMaxDynamicSharedMemorySize, SMEMFA);

    // 1) all prep in one launch
    prep_k<<<10016, 256>>>(queries, keys, Wq, Wk, Wv, fw1, gin, gw, f1t, S1);

    // 2) projections q|k|v in ONE batched launch (z = 0,1,2)
    gemm_mma<128, 0, true><<<dim3(DD / 128, MTOT / 128, 3), 256, SMEMG>>>(
        gin, DD, MD, 0,  gw, DD, (long)DD * DD, 0,  1.0f, DD, 1,
        gqkv, DD, MD, 0, nullptr);

    // 3) fused flash attention + residual -> res
    flash_attn_k<<<dim3(TT / 128, BB * HH), 256, SMEMFA>>>(
        gqkv, gqkv + MD, gqkv + 2 * MD, queries, res);

    // 4) FFN1: relu + per-batch column sums into S1
    gemm_mma<128, 2, false><<<dim3(FF / 128, MTOT / 128, 1), 256, SMEMG>>>(
        res, DD, 0, 0,  f1t, DD, 0, 0,  1.0f, DD, 1,
        nullptr, 0, 0, 0, S1);

    // 5) out = mean_t(res) + (S1/T) @ fw2   (parallel partials + reduce)
    final2_k<<<dim3(8, BB), 512>>>(res, S1, fw2, part);
    final3_k<<<BB, 512>>>(part, out);
}